// round 2
// baseline (speedup 1.0000x reference)
#include <cuda_runtime.h>
#include <cstdint>

#define D_MODEL 2048
#define R_DIM   512
#define N_HEADS 16
#define D_K     32
#define B_SZ    2
#define S_LEN   2048
#define M_ROWS  (B_SZ * S_LEN)   // 4096

// Scratch: Q, K, V, O each (4096 x 512) fp32 = 8MB -> 32MB total
__device__ float g_scratch[4ull * M_ROWS * R_DIM];

// ---------------------------------------------------------------------------
// GEMM: C[M,N] = A[M,K] @ B[N,K]^T + bias[N]   (both operands K-major)
// 128x128 block tile, BK=8, 256 threads, 8x8 per-thread micro-tile.
// ---------------------------------------------------------------------------
#define BM 128
#define BN 128
#define BKG 8

__device__ __forceinline__ void gemm_body(
    const float* __restrict__ A, const float* __restrict__ Bm,
    const float* __restrict__ bias, float* __restrict__ C,
    int N, int K, int bm, int bn)
{
    __shared__ float As[BKG][BM];
    __shared__ float Bs[BKG][BN];

    const int tid  = threadIdx.x;
    const int warp = tid >> 5;
    const int lane = tid & 31;
    // warp grid 4x2 (rows x cols), thread grid 4x8 inside warp
    const int wr = warp & 3;
    const int wc = warp >> 2;
    const int tr = lane & 3;
    const int tc = lane >> 2;
    const int row0 = wr * 32 + tr * 8;   // 0..127
    const int col0 = wc * 64 + tc * 8;   // 0..127

    const int la_row = tid >> 1;         // 0..127
    const int la_k   = (tid & 1) * 4;    // 0 or 4

    const float* Aptr = A  + (size_t)(bm + la_row) * K + la_k;
    const float* Bptr = Bm + (size_t)(bn + la_row) * K + la_k;

    float acc[8][8];
    #pragma unroll
    for (int i = 0; i < 8; i++)
        #pragma unroll
        for (int j = 0; j < 8; j++) acc[i][j] = 0.f;

    for (int k0 = 0; k0 < K; k0 += BKG) {
        float4 av = *(const float4*)(Aptr + k0);
        float4 bv = *(const float4*)(Bptr + k0);
        __syncthreads();
        As[la_k + 0][la_row] = av.x;
        As[la_k + 1][la_row] = av.y;
        As[la_k + 2][la_row] = av.z;
        As[la_k + 3][la_row] = av.w;
        Bs[la_k + 0][la_row] = bv.x;
        Bs[la_k + 1][la_row] = bv.y;
        Bs[la_k + 2][la_row] = bv.z;
        Bs[la_k + 3][la_row] = bv.w;
        __syncthreads();

        #pragma unroll
        for (int k = 0; k < BKG; k++) {
            float a[8], b[8];
            *(float4*)&a[0] = *(const float4*)&As[k][row0];
            *(float4*)&a[4] = *(const float4*)&As[k][row0 + 4];
            *(float4*)&b[0] = *(const float4*)&Bs[k][col0];
            *(float4*)&b[4] = *(const float4*)&Bs[k][col0 + 4];
            #pragma unroll
            for (int i = 0; i < 8; i++)
                #pragma unroll
                for (int j = 0; j < 8; j++)
                    acc[i][j] = fmaf(a[i], b[j], acc[i][j]);
        }
    }

    #pragma unroll
    for (int i = 0; i < 8; i++) {
        float* crow = C + (size_t)(bm + row0 + i) * N + bn + col0;
        #pragma unroll
        for (int j = 0; j < 8; j += 4) {
            float4 v;
            v.x = acc[i][j + 0] + bias[bn + col0 + j + 0];
            v.y = acc[i][j + 1] + bias[bn + col0 + j + 1];
            v.z = acc[i][j + 2] + bias[bn + col0 + j + 2];
            v.w = acc[i][j + 3] + bias[bn + col0 + j + 3];
            *(float4*)(crow + j) = v;
        }
    }
}

__global__ __launch_bounds__(256) void gemm_nt_kernel(
    const float* __restrict__ A, const float* __restrict__ Bm,
    const float* __restrict__ bias, float* __restrict__ C, int N, int K)
{
    gemm_body(A, Bm, bias, C, N, K, blockIdx.y * BM, blockIdx.x * BN);
}

// Fused QKV: blockIdx.z selects projection (0=Q, 1=K, 2=V)
__global__ __launch_bounds__(256) void gemm_qkv_kernel(
    const float* __restrict__ X,
    const float* __restrict__ Wq, const float* __restrict__ Wk, const float* __restrict__ Wv,
    const float* __restrict__ bq, const float* __restrict__ bk, const float* __restrict__ bv,
    float* __restrict__ Q, float* __restrict__ Kd, float* __restrict__ Vd)
{
    const float* W; const float* bias; float* C;
    if (blockIdx.z == 0)      { W = Wq; bias = bq; C = Q;  }
    else if (blockIdx.z == 1) { W = Wk; bias = bk; C = Kd; }
    else                      { W = Wv; bias = bv; C = Vd; }
    gemm_body(X, W, bias, C, R_DIM, D_MODEL, blockIdx.y * BM, blockIdx.x * BN);
}

// ---------------------------------------------------------------------------
// Flash attention: one thread per query row. d_k = 32 in registers;
// online softmax is thread-local (no cross-thread reductions).
// Grid: (S/BQ, B*H), 128 threads per block.
// ---------------------------------------------------------------------------
#define BQ  128
#define BKV 32

__global__ __launch_bounds__(128) void attn_kernel(
    const float* __restrict__ Q, const float* __restrict__ K,
    const float* __restrict__ V, const int* __restrict__ mask,
    float* __restrict__ O)
{
    __shared__ float Qs[BQ][D_K + 1];   // +1 pad: conflict-free per-row reads
    __shared__ float Ks[BKV][D_K];
    __shared__ float Vs[BKV][D_K];
    __shared__ int   Ms[BKV];

    const int tid = threadIdx.x;
    const int bh  = blockIdx.y;
    const int b   = bh / N_HEADS;
    const int h   = bh % N_HEADS;
    const int q0  = blockIdx.x * BQ;
    const size_t rowbase = (size_t)(b * S_LEN) * R_DIM + h * D_K;

    // Stage Q tile through smem (coalesced global), then rows -> registers
    for (int i = tid; i < BQ * (D_K / 4); i += 128) {
        int r  = i >> 3;
        int c4 = (i & 7) << 2;
        float4 v = *(const float4*)&Q[rowbase + (size_t)(q0 + r) * R_DIM + c4];
        Qs[r][c4 + 0] = v.x; Qs[r][c4 + 1] = v.y;
        Qs[r][c4 + 2] = v.z; Qs[r][c4 + 3] = v.w;
    }
    __syncthreads();

    const float scale = 0.17677669529663687f;   // 1/sqrt(32)
    float q[D_K];
    #pragma unroll
    for (int d = 0; d < D_K; d++) q[d] = Qs[tid][d] * scale;

    float m = -1e30f, l = 0.f;
    float o[D_K];
    #pragma unroll
    for (int d = 0; d < D_K; d++) o[d] = 0.f;

    for (int k0 = 0; k0 < S_LEN; k0 += BKV) {
        __syncthreads();   // protect Ks/Vs from previous iteration readers
        for (int i = tid; i < BKV * (D_K / 4); i += 128) {
            int r  = i >> 3;
            int c4 = (i & 7) << 2;
            size_t off = rowbase + (size_t)(k0 + r) * R_DIM + c4;
            *(float4*)&Ks[r][c4] = *(const float4*)&K[off];
            *(float4*)&Vs[r][c4] = *(const float4*)&V[off];
        }
        if (tid < BKV) Ms[tid] = mask[b * S_LEN + k0 + tid];
        __syncthreads();

        float s[BKV];
        float mt = m;
        #pragma unroll
        for (int j = 0; j < BKV; j++) {
            float acc = 0.f;
            #pragma unroll
            for (int d = 0; d < D_K; d++)
                acc = fmaf(q[d], Ks[j][d], acc);
            if (Ms[j] == 0) acc = -1e30f;
            s[j] = acc;
            mt = fmaxf(mt, acc);
        }
        float corr = __expf(m - mt);
        l *= corr;
        #pragma unroll
        for (int d = 0; d < D_K; d++) o[d] *= corr;
        #pragma unroll
        for (int j = 0; j < BKV; j++) {
            float p = __expf(s[j] - mt);
            l += p;
            #pragma unroll
            for (int d = 0; d < D_K; d++)
                o[d] = fmaf(p, Vs[j][d], o[d]);
        }
        m = mt;
    }

    const float inv = 1.0f / l;
    float* orow = O + rowbase + (size_t)(q0 + tid) * R_DIM;   // (B,S,R) layout
    #pragma unroll
    for (int d = 0; d < D_K; d += 4) {
        float4 v;
        v.x = o[d + 0] * inv; v.y = o[d + 1] * inv;
        v.z = o[d + 2] * inv; v.w = o[d + 3] * inv;
        *(float4*)&orow[d] = v;
    }
}

// ---------------------------------------------------------------------------
extern "C" void kernel_launch(void* const* d_in, const int* in_sizes, int n_in,
                              void* d_out, int out_size)
{
    const float* x    = (const float*)d_in[0];
    const float* Wq   = (const float*)d_in[1];
    const float* bq   = (const float*)d_in[2];
    const float* Wk   = (const float*)d_in[3];
    const float* bk   = (const float*)d_in[4];
    const float* Wv   = (const float*)d_in[5];
    const float* bv   = (const float*)d_in[6];
    const float* Wo   = (const float*)d_in[7];
    const float* bo   = (const float*)d_in[8];
    const int*   mask = (const int*)d_in[9];
    float* out = (float*)d_out;

    float* base = nullptr;
    cudaGetSymbolAddress((void**)&base, g_scratch);
    float* Qb = base;
    float* Kb = Qb + (size_t)M_ROWS * R_DIM;
    float* Vb = Kb + (size_t)M_ROWS * R_DIM;
    float* Ob = Vb + (size_t)M_ROWS * R_DIM;

    dim3 blk(256);

    // 1) fused QKV projections: (4096x2048) @ (512x2048)^T, z = {Q,K,V}
    dim3 g_qkv(R_DIM / BN, M_ROWS / BM, 3);
    gemm_qkv_kernel<<<g_qkv, blk>>>(x, Wq, Wk, Wv, bq, bk, bv, Qb, Kb, Vb);

    // 2) flash attention per (b,h), output directly in (B,S,R) layout
    dim3 g_attn(S_LEN / BQ, B_SZ * N_HEADS);
    attn_kernel<<<g_attn, 128>>>(Qb, Kb, Vb, mask, Ob);

    // 3) output projection: (4096x512) @ (2048x512)^T + bo
    dim3 g_out(D_MODEL / BN, M_ROWS / BM);
    gemm_nt_kernel<<<g_out, blk>>>(Ob, Wo, bo, out, D_MODEL, R_DIM);
}

// round 3
// speedup vs baseline: 1.0136x; 1.0136x over previous
#include <cuda_runtime.h>
#include <cstdint>

#define D_MODEL 2048
#define R_DIM   512
#define N_HEADS 16
#define D_K     32
#define B_SZ    2
#define S_LEN   2048
#define M_ROWS  (B_SZ * S_LEN)   // 4096

typedef unsigned long long u64;

// Scratch: Q, K, V, O each (4096 x 512) fp32 = 8MB -> 32MB total
__device__ float g_scratch[4ull * M_ROWS * R_DIM];

// ---------------------------------------------------------------------------
// Packed f32x2 helpers (Blackwell dual-issue fp32 path; exact IEEE fp32 math)
// ---------------------------------------------------------------------------
__device__ __forceinline__ u64 pack2(float x, float y) {
    u64 r; asm("mov.b64 %0, {%1, %2};" : "=l"(r) : "f"(x), "f"(y)); return r;
}
__device__ __forceinline__ u64 dup2(float x) {
    u64 r; asm("mov.b64 %0, {%1, %1};" : "=l"(r) : "f"(x)); return r;
}
__device__ __forceinline__ float2 unpack2(u64 v) {
    float2 r; asm("mov.b64 {%0, %1}, %2;" : "=f"(r.x), "=f"(r.y) : "l"(v)); return r;
}
__device__ __forceinline__ void ffma2(u64& d, u64 a, u64 b) {
    asm("fma.rn.f32x2 %0, %1, %2, %0;" : "+l"(d) : "l"(a), "l"(b));
}

// ---------------------------------------------------------------------------
// GEMM: C[M,N] = A[M,K] @ B[N,K]^T + bias[N]  (both operands K-major)
// 64x128 block tile, BK=16, 256 threads, 4x8 per-thread micro-tile,
// accumulators packed f32x2 along N (4 rows x 4 pairs).
// ---------------------------------------------------------------------------
#define BM 64
#define BN 128
#define BKG 16
#define PAD 4

__device__ __forceinline__ void gemm_body(
    const float* __restrict__ A, const float* __restrict__ Bm,
    const float* __restrict__ bias, float* __restrict__ C,
    int N, int K, int bm, int bn)
{
    __shared__ __align__(16) float As[BKG][BM + PAD];
    __shared__ __align__(16) float Bs[BKG][BN + PAD];

    const int tid  = threadIdx.x;
    const int warp = tid >> 5;
    const int lane = tid & 31;
    // warp grid 2x4 (rows x cols), thread grid 8x4 inside warp
    const int wr = warp & 1;
    const int wc = warp >> 1;
    const int tr = lane & 7;
    const int tc = lane >> 3;
    const int row0 = wr * 32 + tr * 4;   // 0..63
    const int col0 = wc * 32 + tc * 8;   // 0..127

    const int ld_row = tid >> 2;         // 0..63
    const int ld_k   = (tid & 3) * 4;    // 0,4,8,12

    const float* Ap  = A  + (size_t)(bm + ld_row) * K + ld_k;
    const float* Bp0 = Bm + (size_t)(bn + ld_row) * K + ld_k;
    const float* Bp1 = Bm + (size_t)(bn + ld_row + 64) * K + ld_k;

    u64 acc[4][4];
    #pragma unroll
    for (int i = 0; i < 4; i++)
        #pragma unroll
        for (int j = 0; j < 4; j++) acc[i][j] = 0ull;

    for (int k0 = 0; k0 < K; k0 += BKG) {
        float4 av  = *(const float4*)(Ap  + k0);
        float4 bv0 = *(const float4*)(Bp0 + k0);
        float4 bv1 = *(const float4*)(Bp1 + k0);
        __syncthreads();
        As[ld_k + 0][ld_row] = av.x;
        As[ld_k + 1][ld_row] = av.y;
        As[ld_k + 2][ld_row] = av.z;
        As[ld_k + 3][ld_row] = av.w;
        Bs[ld_k + 0][ld_row] = bv0.x;
        Bs[ld_k + 1][ld_row] = bv0.y;
        Bs[ld_k + 2][ld_row] = bv0.z;
        Bs[ld_k + 3][ld_row] = bv0.w;
        Bs[ld_k + 0][ld_row + 64] = bv1.x;
        Bs[ld_k + 1][ld_row + 64] = bv1.y;
        Bs[ld_k + 2][ld_row + 64] = bv1.z;
        Bs[ld_k + 3][ld_row + 64] = bv1.w;
        __syncthreads();

        #pragma unroll
        for (int k = 0; k < BKG; k++) {
            float4 af = *(const float4*)&As[k][row0];
            const ulonglong2* bp = (const ulonglong2*)&Bs[k][col0];
            ulonglong2 b0 = bp[0];
            ulonglong2 b1 = bp[1];
            u64 a0 = dup2(af.x), a1 = dup2(af.y), a2 = dup2(af.z), a3 = dup2(af.w);
            ffma2(acc[0][0], a0, b0.x); ffma2(acc[0][1], a0, b0.y);
            ffma2(acc[0][2], a0, b1.x); ffma2(acc[0][3], a0, b1.y);
            ffma2(acc[1][0], a1, b0.x); ffma2(acc[1][1], a1, b0.y);
            ffma2(acc[1][2], a1, b1.x); ffma2(acc[1][3], a1, b1.y);
            ffma2(acc[2][0], a2, b0.x); ffma2(acc[2][1], a2, b0.y);
            ffma2(acc[2][2], a2, b1.x); ffma2(acc[2][3], a2, b1.y);
            ffma2(acc[3][0], a3, b0.x); ffma2(acc[3][1], a3, b0.y);
            ffma2(acc[3][2], a3, b1.x); ffma2(acc[3][3], a3, b1.y);
        }
    }

    #pragma unroll
    for (int i = 0; i < 4; i++) {
        float* crow = C + (size_t)(bm + row0 + i) * N + bn + col0;
        float outv[8];
        #pragma unroll
        for (int jp = 0; jp < 4; jp++) {
            float2 v = unpack2(acc[i][jp]);
            outv[2 * jp + 0] = v.x + bias[bn + col0 + 2 * jp + 0];
            outv[2 * jp + 1] = v.y + bias[bn + col0 + 2 * jp + 1];
        }
        *(float4*)(crow + 0) = *(float4*)&outv[0];
        *(float4*)(crow + 4) = *(float4*)&outv[4];
    }
}

__global__ __launch_bounds__(256) void gemm_nt_kernel(
    const float* __restrict__ A, const float* __restrict__ Bm,
    const float* __restrict__ bias, float* __restrict__ C, int N, int K)
{
    gemm_body(A, Bm, bias, C, N, K, blockIdx.y * BM, blockIdx.x * BN);
}

// Fused QKV: blockIdx.z selects projection (0=Q, 1=K, 2=V)
__global__ __launch_bounds__(256) void gemm_qkv_kernel(
    const float* __restrict__ X,
    const float* __restrict__ Wq, const float* __restrict__ Wk, const float* __restrict__ Wv,
    const float* __restrict__ bq, const float* __restrict__ bk, const float* __restrict__ bv,
    float* __restrict__ Q, float* __restrict__ Kd, float* __restrict__ Vd)
{
    const float* W; const float* bias; float* C;
    if (blockIdx.z == 0)      { W = Wq; bias = bq; C = Q;  }
    else if (blockIdx.z == 1) { W = Wk; bias = bk; C = Kd; }
    else                      { W = Wv; bias = bv; C = Vd; }
    gemm_body(X, W, bias, C, R_DIM, D_MODEL, blockIdx.y * BM, blockIdx.x * BN);
}

// ---------------------------------------------------------------------------
// Flash attention: one thread per query row, d_k=32 in registers (f32x2 pairs),
// online softmax is entirely thread-local.
// ---------------------------------------------------------------------------
#define BQ  128
#define BKV 32

__global__ __launch_bounds__(128) void attn_kernel(
    const float* __restrict__ Q, const float* __restrict__ K,
    const float* __restrict__ V, const int* __restrict__ mask,
    float* __restrict__ O)
{
    __shared__ __align__(16) float Qs[BQ][D_K + 1];
    __shared__ __align__(16) float Ks[BKV][D_K];
    __shared__ __align__(16) float Vs[BKV][D_K];
    __shared__ int Ms[BKV];

    const int tid = threadIdx.x;
    const int bh  = blockIdx.y;
    const int b   = bh / N_HEADS;
    const int h   = bh % N_HEADS;
    const int q0  = blockIdx.x * BQ;
    const size_t rowbase = (size_t)(b * S_LEN) * R_DIM + h * D_K;

    for (int i = tid; i < BQ * (D_K / 4); i += 128) {
        int r  = i >> 3;
        int c4 = (i & 7) << 2;
        float4 v = *(const float4*)&Q[rowbase + (size_t)(q0 + r) * R_DIM + c4];
        Qs[r][c4 + 0] = v.x; Qs[r][c4 + 1] = v.y;
        Qs[r][c4 + 2] = v.z; Qs[r][c4 + 3] = v.w;
    }
    __syncthreads();

    const float scale = 0.17677669529663687f;   // 1/sqrt(32)
    u64 qp[D_K / 2];
    #pragma unroll
    for (int d2 = 0; d2 < D_K / 2; d2++)
        qp[d2] = pack2(Qs[tid][2 * d2] * scale, Qs[tid][2 * d2 + 1] * scale);

    float m = -1e30f, l = 0.f;
    u64 op[D_K / 2];
    #pragma unroll
    for (int d2 = 0; d2 < D_K / 2; d2++) op[d2] = 0ull;

    for (int k0 = 0; k0 < S_LEN; k0 += BKV) {
        __syncthreads();
        for (int i = tid; i < BKV * (D_K / 4); i += 128) {
            int r  = i >> 3;
            int c4 = (i & 7) << 2;
            size_t off = rowbase + (size_t)(k0 + r) * R_DIM + c4;
            *(float4*)&Ks[r][c4] = *(const float4*)&K[off];
            *(float4*)&Vs[r][c4] = *(const float4*)&V[off];
        }
        if (tid < BKV) Ms[tid] = mask[b * S_LEN + k0 + tid];
        __syncthreads();

        float s[BKV];
        float mt = m;
        #pragma unroll
        for (int j = 0; j < BKV; j++) {
            const ulonglong2* kp = (const ulonglong2*)&Ks[j][0];
            u64 accp = 0ull;
            #pragma unroll
            for (int c = 0; c < D_K / 4; c++) {
                ulonglong2 kk = kp[c];
                ffma2(accp, qp[2 * c + 0], kk.x);
                ffma2(accp, qp[2 * c + 1], kk.y);
            }
            float2 ar = unpack2(accp);
            float sc = ar.x + ar.y;
            if (Ms[j] == 0) sc = -1e30f;
            s[j] = sc;
            mt = fmaxf(mt, sc);
        }
        float corr = __expf(m - mt);
        l *= corr;
        u64 corrp = dup2(corr);
        #pragma unroll
        for (int d2 = 0; d2 < D_K / 2; d2++) {
            // op *= corr  (fma with zero addend via mul)
            asm("mul.rn.f32x2 %0, %0, %1;" : "+l"(op[d2]) : "l"(corrp));
        }
        #pragma unroll
        for (int j = 0; j < BKV; j++) {
            float p = __expf(s[j] - mt);
            l += p;
            u64 pp = dup2(p);
            const ulonglong2* vp = (const ulonglong2*)&Vs[j][0];
            #pragma unroll
            for (int c = 0; c < D_K / 4; c++) {
                ulonglong2 vv = vp[c];
                ffma2(op[2 * c + 0], pp, vv.x);
                ffma2(op[2 * c + 1], pp, vv.y);
            }
        }
        m = mt;
    }

    const float inv = 1.0f / l;
    float* orow = O + rowbase + (size_t)(q0 + tid) * R_DIM;   // (B,S,R) layout
    #pragma unroll
    for (int d2 = 0; d2 < D_K / 2; d2 += 2) {
        float2 v0 = unpack2(op[d2]);
        float2 v1 = unpack2(op[d2 + 1]);
        float4 v;
        v.x = v0.x * inv; v.y = v0.y * inv;
        v.z = v1.x * inv; v.w = v1.y * inv;
        *(float4*)&orow[2 * d2] = v;
    }
}

// ---------------------------------------------------------------------------
extern "C" void kernel_launch(void* const* d_in, const int* in_sizes, int n_in,
                              void* d_out, int out_size)
{
    const float* x    = (const float*)d_in[0];
    const float* Wq   = (const float*)d_in[1];
    const float* bq   = (const float*)d_in[2];
    const float* Wk   = (const float*)d_in[3];
    const float* bk   = (const float*)d_in[4];
    const float* Wv   = (const float*)d_in[5];
    const float* bv   = (const float*)d_in[6];
    const float* Wo   = (const float*)d_in[7];
    const float* bo   = (const float*)d_in[8];
    const int*   mask = (const int*)d_in[9];
    float* out = (float*)d_out;

    float* base = nullptr;
    cudaGetSymbolAddress((void**)&base, g_scratch);
    float* Qb = base;
    float* Kb = Qb + (size_t)M_ROWS * R_DIM;
    float* Vb = Kb + (size_t)M_ROWS * R_DIM;
    float* Ob = Vb + (size_t)M_ROWS * R_DIM;

    dim3 blk(256);

    // 1) fused QKV projections: (4096x2048) @ (512x2048)^T, z = {Q,K,V}
    dim3 g_qkv(R_DIM / BN, M_ROWS / BM, 3);
    gemm_qkv_kernel<<<g_qkv, blk>>>(x, Wq, Wk, Wv, bq, bk, bv, Qb, Kb, Vb);

    // 2) flash attention per (b,h), output directly in (B,S,R) layout
    dim3 g_attn(S_LEN / BQ, B_SZ * N_HEADS);
    attn_kernel<<<g_attn, 128>>>(Qb, Kb, Vb, mask, Ob);

    // 3) output projection: (4096x512) @ (2048x512)^T + bo
    dim3 g_out(D_MODEL / BN, M_ROWS / BM);
    gemm_nt_kernel<<<g_out, blk>>>(Ob, Wo, bo, out, D_MODEL, R_DIM);
}

// round 6
// speedup vs baseline: 1.4184x; 1.3995x over previous
#include <cuda_runtime.h>
#include <cuda_bf16.h>
#include <cstdint>

#define D_MODEL 2048
#define R_DIM   512
#define N_HEADS 16
#define D_K     32
#define B_SZ    2
#define S_LEN   2048
#define M_ROWS  (B_SZ * S_LEN)   // 4096

typedef unsigned long long u64;
typedef uint32_t u32;

// ---------------------------------------------------------------------------
// Scratch
// ---------------------------------------------------------------------------
// fp32: Q, K, V each (4096 x 512)
__device__ float g_f32[3ull * M_ROWS * R_DIM];

// bf16 hi/lo split storage:
//   x      : 4096*2048            @ 0
//   Wq/k/v : 3 * 512*2048         @ 8388608
//   Wo     : 2048*512             @ 11534336
//   O(attn): 4096*512             @ 12582912
#define X_OFF   0ull
#define W_OFF   8388608ull
#define WSZ     1048576ull
#define WO_OFF  11534336ull
#define O_OFF   12582912ull
#define SPLIT_TOTAL 14680064ull
__device__ __nv_bfloat16 g_hi[SPLIT_TOTAL];
__device__ __nv_bfloat16 g_lo[SPLIT_TOTAL];

// ---------------------------------------------------------------------------
// PTX helpers (base ISA only: mma.sync / ldmatrix / cp.async)
// ---------------------------------------------------------------------------
__device__ __forceinline__ u32 smem_u32(const void* p) {
    u32 a;
    asm("{ .reg .u64 t; cvta.to.shared.u64 t, %1; cvt.u32.u64 %0, t; }" : "=r"(a) : "l"(p));
    return a;
}
__device__ __forceinline__ void ldsm_x4(u32& r0, u32& r1, u32& r2, u32& r3, u32 addr) {
    asm volatile("ldmatrix.sync.aligned.m8n8.x4.shared.b16 {%0,%1,%2,%3}, [%4];"
                 : "=r"(r0), "=r"(r1), "=r"(r2), "=r"(r3) : "r"(addr));
}
__device__ __forceinline__ void mma_bf16(float* d, const u32* a, const u32* b) {
    asm volatile(
        "mma.sync.aligned.m16n8k16.row.col.f32.bf16.bf16.f32 "
        "{%0,%1,%2,%3}, {%4,%5,%6,%7}, {%8,%9}, {%0,%1,%2,%3};"
        : "+f"(d[0]), "+f"(d[1]), "+f"(d[2]), "+f"(d[3])
        : "r"(a[0]), "r"(a[1]), "r"(a[2]), "r"(a[3]), "r"(b[0]), "r"(b[1]));
}
__device__ __forceinline__ void cp16(u32 saddr, const void* g) {
    asm volatile("cp.async.cg.shared.global [%0], [%1], 16;" :: "r"(saddr), "l"(g) : "memory");
}
__device__ __forceinline__ void cp_commit() {
    asm volatile("cp.async.commit_group;" ::: "memory");
}

// ---------------------------------------------------------------------------
// fp32 -> bf16 hi/lo split conversion
// ---------------------------------------------------------------------------
__global__ __launch_bounds__(256) void convert_split_kernel(
    const float* __restrict__ src, __nv_bfloat16* __restrict__ hi,
    __nv_bfloat16* __restrict__ lo, int n4)
{
    for (int i = blockIdx.x * blockDim.x + threadIdx.x; i < n4; i += gridDim.x * blockDim.x) {
        float4 v = ((const float4*)src)[i];
        __nv_bfloat16 h0 = __float2bfloat16(v.x);
        __nv_bfloat16 h1 = __float2bfloat16(v.y);
        __nv_bfloat16 h2 = __float2bfloat16(v.z);
        __nv_bfloat16 h3 = __float2bfloat16(v.w);
        __nv_bfloat16 l0 = __float2bfloat16(v.x - __bfloat162float(h0));
        __nv_bfloat16 l1 = __float2bfloat16(v.y - __bfloat162float(h1));
        __nv_bfloat16 l2 = __float2bfloat16(v.z - __bfloat162float(h2));
        __nv_bfloat16 l3 = __float2bfloat16(v.w - __bfloat162float(h3));
        __nv_bfloat162 ph0; ph0.x = h0; ph0.y = h1;
        __nv_bfloat162 ph1; ph1.x = h2; ph1.y = h3;
        __nv_bfloat162 pl0; pl0.x = l0; pl0.y = l1;
        __nv_bfloat162 pl1; pl1.x = l2; pl1.y = l3;
        ((__nv_bfloat162*)hi)[2 * i + 0] = ph0;
        ((__nv_bfloat162*)hi)[2 * i + 1] = ph1;
        ((__nv_bfloat162*)lo)[2 * i + 0] = pl0;
        ((__nv_bfloat162*)lo)[2 * i + 1] = pl1;
    }
}

// ---------------------------------------------------------------------------
// HMMA bf16-split GEMM: C[M,N] = Ah@Bh^T + Ah@Bl^T + Al@Bh^T + bias
// A [M,K] row-major, B [N,K] row-major (both K-major).
// Block 128x128, BK=64 (128B rows, SW128 swizzle), 8 warps (4M x 2N),
// warp tile 32x64, mma m16n8k16, cp.async 2-stage double buffer.
// ---------------------------------------------------------------------------
#define BM 128
#define BN 128
#define BK 64

#define TILE_B      (128 * 128)           // one 128-row x 128B tile
#define STAGE_BYTES (4 * TILE_B)          // Ah, Al, Bh, Bl
#define SM_TOTAL    (2 * STAGE_BYTES)     // 131072

__device__ __forceinline__ void gemm_hmma(
    const __nv_bfloat16* __restrict__ ah, const __nv_bfloat16* __restrict__ al,
    const __nv_bfloat16* __restrict__ bh, const __nv_bfloat16* __restrict__ bl,
    const float* __restrict__ bias, float* __restrict__ C,
    int K, int ldc, int bm, int bn)
{
    extern __shared__ char smem[];
    const u32 sbase = smem_u32(smem);
    const int tid  = threadIdx.x;
    const int lane = tid & 31;
    const int wid  = tid >> 5;
    const int wm   = wid & 3;    // 0..3  -> rows wm*32
    const int wn   = wid >> 2;   // 0..1  -> cols wn*64

    float acc[2][8][4];
    #pragma unroll
    for (int mt = 0; mt < 2; mt++)
        #pragma unroll
        for (int nt = 0; nt < 8; nt++)
            #pragma unroll
            for (int r = 0; r < 4; r++) acc[mt][nt][r] = 0.f;

    // ---- loader: 4096 16B chunks per stage (Ah,Al,Bh,Bl x 1024) ----
    auto load_stage = [&](int c, int stage) {
        const int k0 = c * BK;
        const u32 sb = sbase + stage * STAGE_BYTES;
        #pragma unroll
        for (int t = 0; t < 16; t++) {
            int i   = tid + t * 256;
            int arr = i >> 10;           // 0:Ah 1:Al 2:Bh 3:Bl
            int ch  = i & 1023;
            int row = ch >> 3;
            int cc  = ch & 7;
            u32 soff = (u32)arr * TILE_B + (u32)row * 128 + (u32)((cc ^ (row & 7)) << 4);
            const __nv_bfloat16* g;
            if (arr == 0)      g = ah + (size_t)(bm + row) * K + k0 + cc * 8;
            else if (arr == 1) g = al + (size_t)(bm + row) * K + k0 + cc * 8;
            else if (arr == 2) g = bh + (size_t)(bn + row) * K + k0 + cc * 8;
            else               g = bl + (size_t)(bn + row) * K + k0 + cc * 8;
            cp16(sb + soff, g);
        }
        cp_commit();
    };

    // ---- compute one staged K-chunk (4 k16 steps) ----
    auto compute_stage = [&](int stage) {
        const u32 sb = sbase + stage * STAGE_BYTES;
        #pragma unroll
        for (int ks = 0; ks < 4; ks++) {
            u32 a_h[2][4], a_l[2][4], b_h[8][2], b_l[8][2];
            // A fragments: rows wm*32 + mt*16, lane mapping row=lane%16, kchunk=2ks+lane/16
            #pragma unroll
            for (int mt = 0; mt < 2; mt++) {
                int row = wm * 32 + mt * 16 + (lane & 15);
                u32 koff = (u32)(((2 * ks + (lane >> 4)) ^ (row & 7)) << 4);
                u32 addr = sb + (u32)row * 128 + koff;
                ldsm_x4(a_h[mt][0], a_h[mt][1], a_h[mt][2], a_h[mt][3], addr);
                ldsm_x4(a_l[mt][0], a_l[mt][1], a_l[mt][2], a_l[mt][3], addr + TILE_B);
            }
            // B fragments: pair np covers n-tiles 2np, 2np+1 (rows np*16..+15)
            #pragma unroll
            for (int np = 0; np < 4; np++) {
                int row = wn * 64 + np * 16 + (lane & 15);
                u32 koff = (u32)(((2 * ks + (lane >> 4)) ^ (row & 7)) << 4);
                u32 addr = sb + 2u * TILE_B + (u32)row * 128 + koff;
                u32 r0, r1, r2, r3;
                ldsm_x4(r0, r1, r2, r3, addr);
                b_h[2 * np][0] = r0; b_h[2 * np][1] = r2;
                b_h[2 * np + 1][0] = r1; b_h[2 * np + 1][1] = r3;
                ldsm_x4(r0, r1, r2, r3, addr + TILE_B);
                b_l[2 * np][0] = r0; b_l[2 * np][1] = r2;
                b_l[2 * np + 1][0] = r1; b_l[2 * np + 1][1] = r3;
            }
            // 3-pass split MMA
            #pragma unroll
            for (int mt = 0; mt < 2; mt++)
                #pragma unroll
                for (int nt = 0; nt < 8; nt++) {
                    mma_bf16(acc[mt][nt], a_h[mt], b_h[nt]);
                    mma_bf16(acc[mt][nt], a_h[mt], b_l[nt]);
                    mma_bf16(acc[mt][nt], a_l[mt], b_h[nt]);
                }
        }
    };

    const int nch = K >> 6;
    load_stage(0, 0);
    for (int c = 0; c < nch; c++) {
        if (c + 1 < nch) {
            load_stage(c + 1, (c + 1) & 1);
            asm volatile("cp.async.wait_group 1;" ::: "memory");
        } else {
            asm volatile("cp.async.wait_group 0;" ::: "memory");
        }
        __syncthreads();
        compute_stage(c & 1);
        __syncthreads();
    }

    // ---- epilogue ----
    const int g  = lane >> 2;
    const int tc = lane & 3;
    #pragma unroll
    for (int mt = 0; mt < 2; mt++) {
        #pragma unroll
        for (int nt = 0; nt < 8; nt++) {
            int row = bm + wm * 32 + mt * 16 + g;
            int col = bn + wn * 64 + nt * 8 + 2 * tc;
            float b0 = bias[col], b1 = bias[col + 1];
            float2 v0; v0.x = acc[mt][nt][0] + b0; v0.y = acc[mt][nt][1] + b1;
            float2 v1; v1.x = acc[mt][nt][2] + b0; v1.y = acc[mt][nt][3] + b1;
            *(float2*)&C[(size_t)row * ldc + col]       = v0;
            *(float2*)&C[(size_t)(row + 8) * ldc + col] = v1;
        }
    }
}

// QKV: z selects projection. A = x split, B = W[z] split, C = g_f32 + z*M*R
__global__ __launch_bounds__(256) void qkv_hmma_kernel(
    const float* __restrict__ bq, const float* __restrict__ bk, const float* __restrict__ bv)
{
    const int z = blockIdx.z;
    const float* bias = (z == 0) ? bq : (z == 1) ? bk : bv;
    gemm_hmma(g_hi + X_OFF, g_lo + X_OFF,
              g_hi + W_OFF + (size_t)z * WSZ, g_lo + W_OFF + (size_t)z * WSZ,
              bias, g_f32 + (size_t)z * M_ROWS * R_DIM,
              D_MODEL, R_DIM, blockIdx.y * BM, blockIdx.x * BN);
}

// out-proj: A = attn-output split, B = Wo split, C = d_out
__global__ __launch_bounds__(256) void outproj_hmma_kernel(
    const float* __restrict__ bo, float* __restrict__ out)
{
    gemm_hmma(g_hi + O_OFF, g_lo + O_OFF,
              g_hi + WO_OFF, g_lo + WO_OFF,
              bo, out, R_DIM, D_MODEL, blockIdx.y * BM, blockIdx.x * BN);
}

// ---------------------------------------------------------------------------
// Flash attention (SIMT fp32), one thread per query row. Writes bf16 hi/lo.
// ---------------------------------------------------------------------------
#define BQ  128
#define BKV 32

__device__ __forceinline__ u64 pack2(float x, float y) {
    u64 r; asm("mov.b64 %0, {%1, %2};" : "=l"(r) : "f"(x), "f"(y)); return r;
}
__device__ __forceinline__ u64 dup2(float x) {
    u64 r; asm("mov.b64 %0, {%1, %1};" : "=l"(r) : "f"(x)); return r;
}
__device__ __forceinline__ float2 unpack2(u64 v) {
    float2 r; asm("mov.b64 {%0, %1}, %2;" : "=f"(r.x), "=f"(r.y) : "l"(v)); return r;
}
__device__ __forceinline__ void ffma2(u64& d, u64 a, u64 b) {
    asm("fma.rn.f32x2 %0, %1, %2, %0;" : "+l"(d) : "l"(a), "l"(b));
}

__global__ __launch_bounds__(128) void attn_kernel(
    const float* __restrict__ Q, const float* __restrict__ K,
    const float* __restrict__ V, const int* __restrict__ mask,
    __nv_bfloat16* __restrict__ Oh, __nv_bfloat16* __restrict__ Ol)
{
    __shared__ __align__(16) float Qs[BQ][D_K + 1];
    __shared__ __align__(16) float Ks[BKV][D_K];
    __shared__ __align__(16) float Vs[BKV][D_K];
    __shared__ int Ms[BKV];

    const int tid = threadIdx.x;
    const int bh  = blockIdx.y;
    const int b   = bh / N_HEADS;
    const int h   = bh % N_HEADS;
    const int q0  = blockIdx.x * BQ;
    const size_t rowbase = (size_t)(b * S_LEN) * R_DIM + h * D_K;

    for (int i = tid; i < BQ * (D_K / 4); i += 128) {
        int r  = i >> 3;
        int c4 = (i & 7) << 2;
        float4 v = *(const float4*)&Q[rowbase + (size_t)(q0 + r) * R_DIM + c4];
        Qs[r][c4 + 0] = v.x; Qs[r][c4 + 1] = v.y;
        Qs[r][c4 + 2] = v.z; Qs[r][c4 + 3] = v.w;
    }
    __syncthreads();

    const float scale = 0.17677669529663687f;   // 1/sqrt(32)
    u64 qp[D_K / 2];
    #pragma unroll
    for (int d2 = 0; d2 < D_K / 2; d2++)
        qp[d2] = pack2(Qs[tid][2 * d2] * scale, Qs[tid][2 * d2 + 1] * scale);

    float m = -1e30f, l = 0.f;
    u64 op[D_K / 2];
    #pragma unroll
    for (int d2 = 0; d2 < D_K / 2; d2++) op[d2] = 0ull;

    for (int k0 = 0; k0 < S_LEN; k0 += BKV) {
        __syncthreads();
        for (int i = tid; i < BKV * (D_K / 4); i += 128) {
            int r  = i >> 3;
            int c4 = (i & 7) << 2;
            size_t off = rowbase + (size_t)(k0 + r) * R_DIM + c4;
            *(float4*)&Ks[r][c4] = *(const float4*)&K[off];
            *(float4*)&Vs[r][c4] = *(const float4*)&V[off];
        }
        if (tid < BKV) Ms[tid] = mask[b * S_LEN + k0 + tid];
        __syncthreads();

        float s[BKV];
        float mt = m;
        #pragma unroll
        for (int j = 0; j < BKV; j++) {
            const ulonglong2* kp = (const ulonglong2*)&Ks[j][0];
            u64 accp = 0ull;
            #pragma unroll
            for (int c = 0; c < D_K / 4; c++) {
                ulonglong2 kk = kp[c];
                ffma2(accp, qp[2 * c + 0], kk.x);
                ffma2(accp, qp[2 * c + 1], kk.y);
            }
            float2 ar = unpack2(accp);
            float sc = ar.x + ar.y;
            if (Ms[j] == 0) sc = -1e30f;
            s[j] = sc;
            mt = fmaxf(mt, sc);
        }
        float corr = __expf(m - mt);
        l *= corr;
        u64 corrp = dup2(corr);
        #pragma unroll
        for (int d2 = 0; d2 < D_K / 2; d2++)
            asm("mul.rn.f32x2 %0, %0, %1;" : "+l"(op[d2]) : "l"(corrp));
        #pragma unroll
        for (int j = 0; j < BKV; j++) {
            float p = __expf(s[j] - mt);
            l += p;
            u64 pp = dup2(p);
            const ulonglong2* vp = (const ulonglong2*)&Vs[j][0];
            #pragma unroll
            for (int c = 0; c < D_K / 4; c++) {
                ulonglong2 vv = vp[c];
                ffma2(op[2 * c + 0], pp, vv.x);
                ffma2(op[2 * c + 1], pp, vv.y);
            }
        }
        m = mt;
    }

    const float inv = 1.0f / l;
    __nv_bfloat16* ohrow = Oh + rowbase + (size_t)(q0 + tid) * R_DIM;
    __nv_bfloat16* olrow = Ol + rowbase + (size_t)(q0 + tid) * R_DIM;
    #pragma unroll
    for (int d2 = 0; d2 < D_K / 2; d2++) {
        float2 v = unpack2(op[d2]);
        float f0 = v.x * inv, f1 = v.y * inv;
        __nv_bfloat16 h0 = __float2bfloat16(f0);
        __nv_bfloat16 h1 = __float2bfloat16(f1);
        __nv_bfloat16 l0 = __float2bfloat16(f0 - __bfloat162float(h0));
        __nv_bfloat16 l1 = __float2bfloat16(f1 - __bfloat162float(h1));
        __nv_bfloat162 ph; ph.x = h0; ph.y = h1;
        __nv_bfloat162 pl; pl.x = l0; pl.y = l1;
        *(__nv_bfloat162*)&ohrow[2 * d2] = ph;
        *(__nv_bfloat162*)&olrow[2 * d2] = pl;
    }
}

// ---------------------------------------------------------------------------
extern "C" void kernel_launch(void* const* d_in, const int* in_sizes, int n_in,
                              void* d_out, int out_size)
{
    const float* x    = (const float*)d_in[0];
    const float* Wq   = (const float*)d_in[1];
    const float* bq   = (const float*)d_in[2];
    const float* Wk   = (const float*)d_in[3];
    const float* bk   = (const float*)d_in[4];
    const float* Wv   = (const float*)d_in[5];
    const float* bv   = (const float*)d_in[6];
    const float* Wo   = (const float*)d_in[7];
    const float* bo   = (const float*)d_in[8];
    const int*   mask = (const int*)d_in[9];
    float* out = (float*)d_out;

    float* f32base = nullptr;
    cudaGetSymbolAddress((void**)&f32base, g_f32);
    __nv_bfloat16* hib = nullptr;
    __nv_bfloat16* lob = nullptr;
    cudaGetSymbolAddress((void**)&hib, g_hi);
    cudaGetSymbolAddress((void**)&lob, g_lo);

    float* Qb = f32base;
    float* Kb = Qb + (size_t)M_ROWS * R_DIM;
    float* Vb = Kb + (size_t)M_ROWS * R_DIM;

    cudaFuncSetAttribute(qkv_hmma_kernel, cudaFuncAttributeMaxDynamicSharedMemorySize, SM_TOTAL);
    cudaFuncSetAttribute(outproj_hmma_kernel, cudaFuncAttributeMaxDynamicSharedMemorySize, SM_TOTAL);

    // 1) fp32 -> bf16 hi/lo splits
    convert_split_kernel<<<2048, 256>>>(x,  hib + X_OFF,           lob + X_OFF,           (int)(8388608 / 4));
    convert_split_kernel<<<1024, 256>>>(Wq, hib + W_OFF,           lob + W_OFF,           (int)(WSZ / 4));
    convert_split_kernel<<<1024, 256>>>(Wk, hib + W_OFF + WSZ,     lob + W_OFF + WSZ,     (int)(WSZ / 4));
    convert_split_kernel<<<1024, 256>>>(Wv, hib + W_OFF + 2 * WSZ, lob + W_OFF + 2 * WSZ, (int)(WSZ / 4));
    convert_split_kernel<<<1024, 256>>>(Wo, hib + WO_OFF,          lob + WO_OFF,          (int)(WSZ / 4));

    // 2) QKV projections on HMMA (bf16 split, fp32 accumulate)
    dim3 g_qkv(R_DIM / BN, M_ROWS / BM, 3);     // (4, 32, 3)
    qkv_hmma_kernel<<<g_qkv, 256, SM_TOTAL>>>(bq, bk, bv);

    // 3) flash attention (fp32 SIMT), emits bf16 hi/lo output
    dim3 g_attn(S_LEN / BQ, B_SZ * N_HEADS);
    attn_kernel<<<g_attn, 128>>>(Qb, Kb, Vb, mask, hib + O_OFF, lob + O_OFF);

    // 4) output projection on HMMA
    dim3 g_out(D_MODEL / BN, M_ROWS / BM);      // (16, 32)
    outproj_hmma_kernel<<<g_out, 256, SM_TOTAL>>>(bo, out);
}

// round 7
// speedup vs baseline: 2.7440x; 1.9345x over previous
#include <cuda_runtime.h>
#include <cuda_bf16.h>
#include <cstdint>

#define D_MODEL 2048
#define R_DIM   512
#define N_HEADS 16
#define D_K     32
#define B_SZ    2
#define S_LEN   2048
#define M_ROWS  (B_SZ * S_LEN)   // 4096

typedef unsigned long long u64;
typedef uint32_t u32;

// ---------------------------------------------------------------------------
// Scratch
// ---------------------------------------------------------------------------
// fp32: Q, K, V each (4096 x 512)
__device__ float g_f32[3ull * M_ROWS * R_DIM];

// bf16 hi/lo split storage:
//   x      : 4096*2048            @ 0
//   Wq/k/v : 3 * 512*2048         @ 8388608
//   Wo     : 2048*512             @ 11534336
//   O(attn): 4096*512             @ 12582912
#define X_OFF   0ull
#define W_OFF   8388608ull
#define WSZ     1048576ull
#define WO_OFF  11534336ull
#define O_OFF   12582912ull
#define SPLIT_TOTAL 14680064ull
__device__ __nv_bfloat16 g_hi[SPLIT_TOTAL];
__device__ __nv_bfloat16 g_lo[SPLIT_TOTAL];

// ---------------------------------------------------------------------------
// PTX helpers (base ISA only: mma.sync / ldmatrix / cp.async)
// ---------------------------------------------------------------------------
__device__ __forceinline__ u32 smem_u32(const void* p) {
    u32 a;
    asm("{ .reg .u64 t; cvta.to.shared.u64 t, %1; cvt.u32.u64 %0, t; }" : "=r"(a) : "l"(p));
    return a;
}
__device__ __forceinline__ void ldsm_x4(u32& r0, u32& r1, u32& r2, u32& r3, u32 addr) {
    asm volatile("ldmatrix.sync.aligned.m8n8.x4.shared.b16 {%0,%1,%2,%3}, [%4];"
                 : "=r"(r0), "=r"(r1), "=r"(r2), "=r"(r3) : "r"(addr));
}
__device__ __forceinline__ void ldsm_x4_t(u32& r0, u32& r1, u32& r2, u32& r3, u32 addr) {
    asm volatile("ldmatrix.sync.aligned.m8n8.x4.trans.shared.b16 {%0,%1,%2,%3}, [%4];"
                 : "=r"(r0), "=r"(r1), "=r"(r2), "=r"(r3) : "r"(addr));
}
__device__ __forceinline__ void mma_bf16(float* d, const u32* a, const u32* b) {
    asm volatile(
        "mma.sync.aligned.m16n8k16.row.col.f32.bf16.bf16.f32 "
        "{%0,%1,%2,%3}, {%4,%5,%6,%7}, {%8,%9}, {%0,%1,%2,%3};"
        : "+f"(d[0]), "+f"(d[1]), "+f"(d[2]), "+f"(d[3])
        : "r"(a[0]), "r"(a[1]), "r"(a[2]), "r"(a[3]), "r"(b[0]), "r"(b[1]));
}
__device__ __forceinline__ void cp16(u32 saddr, const void* g) {
    asm volatile("cp.async.cg.shared.global [%0], [%1], 16;" :: "r"(saddr), "l"(g) : "memory");
}
__device__ __forceinline__ void cp_commit() {
    asm volatile("cp.async.commit_group;" ::: "memory");
}
// pack two floats into bf16x2 (lo = x, hi = y); residual pair returned in lo_out
__device__ __forceinline__ u32 pack_split(float x, float y, u32& lo_out) {
    __nv_bfloat162 h = __floats2bfloat162_rn(x, y);
    float hx = __bfloat162float(h.x), hy = __bfloat162float(h.y);
    __nv_bfloat162 l = __floats2bfloat162_rn(x - hx, y - hy);
    lo_out = *reinterpret_cast<u32*>(&l);
    return *reinterpret_cast<u32*>(&h);
}

// ---------------------------------------------------------------------------
// fp32 -> bf16 hi/lo split conversion
// ---------------------------------------------------------------------------
__global__ __launch_bounds__(256) void convert_split_kernel(
    const float* __restrict__ src, __nv_bfloat16* __restrict__ hi,
    __nv_bfloat16* __restrict__ lo, int n4)
{
    for (int i = blockIdx.x * blockDim.x + threadIdx.x; i < n4; i += gridDim.x * blockDim.x) {
        float4 v = ((const float4*)src)[i];
        __nv_bfloat16 h0 = __float2bfloat16(v.x);
        __nv_bfloat16 h1 = __float2bfloat16(v.y);
        __nv_bfloat16 h2 = __float2bfloat16(v.z);
        __nv_bfloat16 h3 = __float2bfloat16(v.w);
        __nv_bfloat16 l0 = __float2bfloat16(v.x - __bfloat162float(h0));
        __nv_bfloat16 l1 = __float2bfloat16(v.y - __bfloat162float(h1));
        __nv_bfloat16 l2 = __float2bfloat16(v.z - __bfloat162float(h2));
        __nv_bfloat16 l3 = __float2bfloat16(v.w - __bfloat162float(h3));
        __nv_bfloat162 ph0; ph0.x = h0; ph0.y = h1;
        __nv_bfloat162 ph1; ph1.x = h2; ph1.y = h3;
        __nv_bfloat162 pl0; pl0.x = l0; pl0.y = l1;
        __nv_bfloat162 pl1; pl1.x = l2; pl1.y = l3;
        ((__nv_bfloat162*)hi)[2 * i + 0] = ph0;
        ((__nv_bfloat162*)hi)[2 * i + 1] = ph1;
        ((__nv_bfloat162*)lo)[2 * i + 0] = pl0;
        ((__nv_bfloat162*)lo)[2 * i + 1] = pl1;
    }
}

// ---------------------------------------------------------------------------
// HMMA bf16-split GEMM (unchanged from round 5 — validated)
// ---------------------------------------------------------------------------
#define BM 128
#define BN 128
#define BK 64

#define TILE_B      (128 * 128)
#define STAGE_BYTES (4 * TILE_B)
#define SM_TOTAL    (2 * STAGE_BYTES)

__device__ __forceinline__ void gemm_hmma(
    const __nv_bfloat16* __restrict__ ah, const __nv_bfloat16* __restrict__ al,
    const __nv_bfloat16* __restrict__ bh, const __nv_bfloat16* __restrict__ bl,
    const float* __restrict__ bias, float* __restrict__ C,
    int K, int ldc, int bm, int bn)
{
    extern __shared__ char smem[];
    const u32 sbase = smem_u32(smem);
    const int tid  = threadIdx.x;
    const int lane = tid & 31;
    const int wid  = tid >> 5;
    const int wm   = wid & 3;
    const int wn   = wid >> 2;

    float acc[2][8][4];
    #pragma unroll
    for (int mt = 0; mt < 2; mt++)
        #pragma unroll
        for (int nt = 0; nt < 8; nt++)
            #pragma unroll
            for (int r = 0; r < 4; r++) acc[mt][nt][r] = 0.f;

    auto load_stage = [&](int c, int stage) {
        const int k0 = c * BK;
        const u32 sb = sbase + stage * STAGE_BYTES;
        #pragma unroll
        for (int t = 0; t < 16; t++) {
            int i   = tid + t * 256;
            int arr = i >> 10;
            int ch  = i & 1023;
            int row = ch >> 3;
            int cc  = ch & 7;
            u32 soff = (u32)arr * TILE_B + (u32)row * 128 + (u32)((cc ^ (row & 7)) << 4);
            const __nv_bfloat16* g;
            if (arr == 0)      g = ah + (size_t)(bm + row) * K + k0 + cc * 8;
            else if (arr == 1) g = al + (size_t)(bm + row) * K + k0 + cc * 8;
            else if (arr == 2) g = bh + (size_t)(bn + row) * K + k0 + cc * 8;
            else               g = bl + (size_t)(bn + row) * K + k0 + cc * 8;
            cp16(sb + soff, g);
        }
        cp_commit();
    };

    auto compute_stage = [&](int stage) {
        const u32 sb = sbase + stage * STAGE_BYTES;
        #pragma unroll
        for (int ks = 0; ks < 4; ks++) {
            u32 a_h[2][4], a_l[2][4], b_h[8][2], b_l[8][2];
            #pragma unroll
            for (int mt = 0; mt < 2; mt++) {
                int row = wm * 32 + mt * 16 + (lane & 15);
                u32 koff = (u32)(((2 * ks + (lane >> 4)) ^ (row & 7)) << 4);
                u32 addr = sb + (u32)row * 128 + koff;
                ldsm_x4(a_h[mt][0], a_h[mt][1], a_h[mt][2], a_h[mt][3], addr);
                ldsm_x4(a_l[mt][0], a_l[mt][1], a_l[mt][2], a_l[mt][3], addr + TILE_B);
            }
            #pragma unroll
            for (int np = 0; np < 4; np++) {
                int row = wn * 64 + np * 16 + (lane & 15);
                u32 koff = (u32)(((2 * ks + (lane >> 4)) ^ (row & 7)) << 4);
                u32 addr = sb + 2u * TILE_B + (u32)row * 128 + koff;
                u32 r0, r1, r2, r3;
                ldsm_x4(r0, r1, r2, r3, addr);
                b_h[2 * np][0] = r0; b_h[2 * np][1] = r2;
                b_h[2 * np + 1][0] = r1; b_h[2 * np + 1][1] = r3;
                ldsm_x4(r0, r1, r2, r3, addr + TILE_B);
                b_l[2 * np][0] = r0; b_l[2 * np][1] = r2;
                b_l[2 * np + 1][0] = r1; b_l[2 * np + 1][1] = r3;
            }
            #pragma unroll
            for (int mt = 0; mt < 2; mt++)
                #pragma unroll
                for (int nt = 0; nt < 8; nt++) {
                    mma_bf16(acc[mt][nt], a_h[mt], b_h[nt]);
                    mma_bf16(acc[mt][nt], a_h[mt], b_l[nt]);
                    mma_bf16(acc[mt][nt], a_l[mt], b_h[nt]);
                }
        }
    };

    const int nch = K >> 6;
    load_stage(0, 0);
    for (int c = 0; c < nch; c++) {
        if (c + 1 < nch) {
            load_stage(c + 1, (c + 1) & 1);
            asm volatile("cp.async.wait_group 1;" ::: "memory");
        } else {
            asm volatile("cp.async.wait_group 0;" ::: "memory");
        }
        __syncthreads();
        compute_stage(c & 1);
        __syncthreads();
    }

    const int g  = lane >> 2;
    const int tc = lane & 3;
    #pragma unroll
    for (int mt = 0; mt < 2; mt++) {
        #pragma unroll
        for (int nt = 0; nt < 8; nt++) {
            int row = bm + wm * 32 + mt * 16 + g;
            int col = bn + wn * 64 + nt * 8 + 2 * tc;
            float b0 = bias[col], b1 = bias[col + 1];
            float2 v0; v0.x = acc[mt][nt][0] + b0; v0.y = acc[mt][nt][1] + b1;
            float2 v1; v1.x = acc[mt][nt][2] + b0; v1.y = acc[mt][nt][3] + b1;
            *(float2*)&C[(size_t)row * ldc + col]       = v0;
            *(float2*)&C[(size_t)(row + 8) * ldc + col] = v1;
        }
    }
}

__global__ __launch_bounds__(256) void qkv_hmma_kernel(
    const float* __restrict__ bq, const float* __restrict__ bk, const float* __restrict__ bv)
{
    const int z = blockIdx.z;
    const float* bias = (z == 0) ? bq : (z == 1) ? bk : bv;
    gemm_hmma(g_hi + X_OFF, g_lo + X_OFF,
              g_hi + W_OFF + (size_t)z * WSZ, g_lo + W_OFF + (size_t)z * WSZ,
              bias, g_f32 + (size_t)z * M_ROWS * R_DIM,
              D_MODEL, R_DIM, blockIdx.y * BM, blockIdx.x * BN);
}

__global__ __launch_bounds__(256) void outproj_hmma_kernel(
    const float* __restrict__ bo, float* __restrict__ out)
{
    gemm_hmma(g_hi + O_OFF, g_lo + O_OFF,
              g_hi + WO_OFF, g_lo + WO_OFF,
              bo, out, R_DIM, D_MODEL, blockIdx.y * BM, blockIdx.x * BN);
}

// ---------------------------------------------------------------------------
// HMMA flash attention.
// CTA: 128 queries x one (b,h); 8 warps, warp = 16 query rows (m16).
// KV chunks of 128. Q/K/V staged to smem as bf16 hi/lo, rows padded to 80B.
// QK^T and P@V both 3-pass hi/lo split MMA, fp32 accum. Online softmax in regs.
// ---------------------------------------------------------------------------
#define ATT_BQ  128
#define ATT_BKV 128
#define ROWB    80          // padded smem row: 32 bf16 = 64B data + 16B pad

#define AQ_H  0
#define AQ_L  10240
#define AK_H  20480
#define AK_L  30720
#define AV_H  40960
#define AV_L  51200
#define AMADD 61440
#define ATT_SMEM 61952

__global__ __launch_bounds__(256, 1) void attn_hmma_kernel(
    const float* __restrict__ Q, const float* __restrict__ K,
    const float* __restrict__ V, const int* __restrict__ mask,
    __nv_bfloat16* __restrict__ Oh, __nv_bfloat16* __restrict__ Ol)
{
    extern __shared__ char smem[];
    const u32 sb = smem_u32(smem);
    const int tid  = threadIdx.x;
    const int lane = tid & 31;
    const int w    = tid >> 5;
    const int bh   = blockIdx.y;
    const int b    = bh >> 4;
    const int h    = bh & 15;
    const int q0   = blockIdx.x * ATT_BQ;
    const int g    = lane >> 2;
    const int tc   = lane & 3;

    // ---- stage Q once (scale folded in), hi/lo split ----
    {
        const int r  = tid >> 1;
        const int d0 = (tid & 1) * 16;
        const float* src = Q + (size_t)(b * S_LEN + q0 + r) * R_DIM + h * D_K + d0;
        __nv_bfloat16 hv[16], lv[16];
        #pragma unroll
        for (int i = 0; i < 16; i += 4) {
            float4 v = *(const float4*)(src + i);
            float f[4] = {v.x * 0.17677669529663687f, v.y * 0.17677669529663687f,
                          v.z * 0.17677669529663687f, v.w * 0.17677669529663687f};
            #pragma unroll
            for (int j = 0; j < 4; j++) {
                __nv_bfloat16 hh = __float2bfloat16(f[j]);
                hv[i + j] = hh;
                lv[i + j] = __float2bfloat16(f[j] - __bfloat162float(hh));
            }
        }
        *(uint4*)(smem + AQ_H + r * ROWB + d0 * 2)      = *(uint4*)&hv[0];
        *(uint4*)(smem + AQ_H + r * ROWB + d0 * 2 + 16) = *(uint4*)&hv[8];
        *(uint4*)(smem + AQ_L + r * ROWB + d0 * 2)      = *(uint4*)&lv[0];
        *(uint4*)(smem + AQ_L + r * ROWB + d0 * 2 + 16) = *(uint4*)&lv[8];
    }
    __syncthreads();

    // preload Q A-fragments (m16, 2 k16 chunks over d=32)
    u32 aqh[2][4], aql[2][4];
    #pragma unroll
    for (int kk = 0; kk < 2; kk++) {
        u32 addr = sb + AQ_H + (u32)(w * 16 + (lane & 15)) * ROWB + kk * 32 + (lane >> 4) * 16;
        ldsm_x4(aqh[kk][0], aqh[kk][1], aqh[kk][2], aqh[kk][3], addr);
        ldsm_x4(aql[kk][0], aql[kk][1], aql[kk][2], aql[kk][3], addr + (AQ_L - AQ_H));
    }

    float m0 = -1e30f, m1 = -1e30f, l0 = 0.f, l1 = 0.f;
    float ao[4][4];
    #pragma unroll
    for (int nt = 0; nt < 4; nt++)
        #pragma unroll
        for (int r = 0; r < 4; r++) ao[nt][r] = 0.f;

    for (int k0 = 0; k0 < S_LEN; k0 += ATT_BKV) {
        __syncthreads();
        // ---- stage K, V hi/lo ----
        {
            const int r  = tid >> 1;
            const int d0 = (tid & 1) * 16;
            const size_t goff = (size_t)(b * S_LEN + k0 + r) * R_DIM + h * D_K + d0;
            const float* ks = K + goff;
            const float* vs = V + goff;
            __nv_bfloat16 kh[16], kl[16], vh[16], vl[16];
            #pragma unroll
            for (int i = 0; i < 16; i += 4) {
                float4 kv = *(const float4*)(ks + i);
                float4 vv = *(const float4*)(vs + i);
                float kf[4] = {kv.x, kv.y, kv.z, kv.w};
                float vf[4] = {vv.x, vv.y, vv.z, vv.w};
                #pragma unroll
                for (int j = 0; j < 4; j++) {
                    __nv_bfloat16 hh = __float2bfloat16(kf[j]);
                    kh[i + j] = hh;
                    kl[i + j] = __float2bfloat16(kf[j] - __bfloat162float(hh));
                    hh = __float2bfloat16(vf[j]);
                    vh[i + j] = hh;
                    vl[i + j] = __float2bfloat16(vf[j] - __bfloat162float(hh));
                }
            }
            *(uint4*)(smem + AK_H + r * ROWB + d0 * 2)      = *(uint4*)&kh[0];
            *(uint4*)(smem + AK_H + r * ROWB + d0 * 2 + 16) = *(uint4*)&kh[8];
            *(uint4*)(smem + AK_L + r * ROWB + d0 * 2)      = *(uint4*)&kl[0];
            *(uint4*)(smem + AK_L + r * ROWB + d0 * 2 + 16) = *(uint4*)&kl[8];
            *(uint4*)(smem + AV_H + r * ROWB + d0 * 2)      = *(uint4*)&vh[0];
            *(uint4*)(smem + AV_H + r * ROWB + d0 * 2 + 16) = *(uint4*)&vh[8];
            *(uint4*)(smem + AV_L + r * ROWB + d0 * 2)      = *(uint4*)&vl[0];
            *(uint4*)(smem + AV_L + r * ROWB + d0 * 2 + 16) = *(uint4*)&vl[8];
        }
        if (tid < ATT_BKV) {
            int mv = mask[b * S_LEN + k0 + tid];
            *(float*)(smem + AMADD + tid * 4) = mv ? 0.f : -1e30f;
        }
        __syncthreads();

        // ---- scores: 128(q per warp-slice 16) x 128(j), 3-pass split ----
        float sc[16][4];
        #pragma unroll
        for (int p8 = 0; p8 < 8; p8++) {
            #pragma unroll
            for (int r = 0; r < 4; r++) { sc[2 * p8][r] = 0.f; sc[2 * p8 + 1][r] = 0.f; }
            #pragma unroll
            for (int kk = 0; kk < 2; kk++) {
                u32 addr = sb + AK_H + (u32)(p8 * 16 + (lane & 15)) * ROWB + kk * 32 + (lane >> 4) * 16;
                u32 rh0, rh1, rh2, rh3, rl0, rl1, rl2, rl3;
                ldsm_x4(rh0, rh1, rh2, rh3, addr);
                ldsm_x4(rl0, rl1, rl2, rl3, addr + (AK_L - AK_H));
                u32 beh[2] = {rh0, rh2}, boh[2] = {rh1, rh3};
                u32 bel[2] = {rl0, rl2}, bol[2] = {rl1, rl3};
                mma_bf16(sc[2 * p8], aqh[kk], beh);
                mma_bf16(sc[2 * p8], aqh[kk], bel);
                mma_bf16(sc[2 * p8], aql[kk], beh);
                mma_bf16(sc[2 * p8 + 1], aqh[kk], boh);
                mma_bf16(sc[2 * p8 + 1], aqh[kk], bol);
                mma_bf16(sc[2 * p8 + 1], aql[kk], boh);
            }
        }

        // ---- online softmax (rows g and g+8) ----
        float mt0 = m0, mt1 = m1;
        #pragma unroll
        for (int nt = 0; nt < 16; nt++) {
            float md0 = *(const float*)(smem + AMADD + (nt * 8 + 2 * tc) * 4);
            float md1 = *(const float*)(smem + AMADD + (nt * 8 + 2 * tc + 1) * 4);
            sc[nt][0] += md0; sc[nt][1] += md1;
            sc[nt][2] += md0; sc[nt][3] += md1;
            mt0 = fmaxf(mt0, fmaxf(sc[nt][0], sc[nt][1]));
            mt1 = fmaxf(mt1, fmaxf(sc[nt][2], sc[nt][3]));
        }
        mt0 = fmaxf(mt0, __shfl_xor_sync(0xFFFFFFFFu, mt0, 1));
        mt0 = fmaxf(mt0, __shfl_xor_sync(0xFFFFFFFFu, mt0, 2));
        mt1 = fmaxf(mt1, __shfl_xor_sync(0xFFFFFFFFu, mt1, 1));
        mt1 = fmaxf(mt1, __shfl_xor_sync(0xFFFFFFFFu, mt1, 2));
        float corr0 = __expf(m0 - mt0);
        float corr1 = __expf(m1 - mt1);
        m0 = mt0; m1 = mt1;
        float ls0 = 0.f, ls1 = 0.f;
        #pragma unroll
        for (int nt = 0; nt < 16; nt++) {
            sc[nt][0] = __expf(sc[nt][0] - m0);
            sc[nt][1] = __expf(sc[nt][1] - m0);
            sc[nt][2] = __expf(sc[nt][2] - m1);
            sc[nt][3] = __expf(sc[nt][3] - m1);
            ls0 += sc[nt][0] + sc[nt][1];
            ls1 += sc[nt][2] + sc[nt][3];
        }
        ls0 += __shfl_xor_sync(0xFFFFFFFFu, ls0, 1);
        ls0 += __shfl_xor_sync(0xFFFFFFFFu, ls0, 2);
        ls1 += __shfl_xor_sync(0xFFFFFFFFu, ls1, 1);
        ls1 += __shfl_xor_sync(0xFFFFFFFFu, ls1, 2);
        l0 = l0 * corr0 + ls0;
        l1 = l1 * corr1 + ls1;
        #pragma unroll
        for (int nt = 0; nt < 4; nt++) {
            ao[nt][0] *= corr0; ao[nt][1] *= corr0;
            ao[nt][2] *= corr1; ao[nt][3] *= corr1;
        }

        // ---- P @ V: A from score regs (hi/lo), B via ldmatrix.trans on V ----
        #pragma unroll
        for (int jc = 0; jc < 8; jc++) {
            u32 ah[4], al[4];
            ah[0] = pack_split(sc[2 * jc][0],     sc[2 * jc][1],     al[0]);
            ah[1] = pack_split(sc[2 * jc][2],     sc[2 * jc][3],     al[1]);
            ah[2] = pack_split(sc[2 * jc + 1][0], sc[2 * jc + 1][1], al[2]);
            ah[3] = pack_split(sc[2 * jc + 1][2], sc[2 * jc + 1][3], al[3]);
            #pragma unroll
            for (int np = 0; np < 2; np++) {
                u32 addr = sb + AV_H
                         + (u32)(jc * 16 + ((lane >> 3) & 1) * 8 + (lane & 7)) * ROWB
                         + (u32)(np * 16 + (lane >> 4) * 8) * 2;
                u32 th0, th1, th2, th3, tl0, tl1, tl2, tl3;
                ldsm_x4_t(th0, th1, th2, th3, addr);
                ldsm_x4_t(tl0, tl1, tl2, tl3, addr + (AV_L - AV_H));
                u32 beh[2] = {th0, th1}, boh[2] = {th2, th3};
                u32 bel[2] = {tl0, tl1}, bol[2] = {tl2, tl3};
                mma_bf16(ao[2 * np], ah, beh);
                mma_bf16(ao[2 * np], ah, bel);
                mma_bf16(ao[2 * np], al, beh);
                mma_bf16(ao[2 * np + 1], ah, boh);
                mma_bf16(ao[2 * np + 1], ah, bol);
                mma_bf16(ao[2 * np + 1], al, boh);
            }
        }
    }

    // ---- epilogue: O /= l, write bf16 hi/lo ----
    const float inv0 = 1.0f / l0;
    const float inv1 = 1.0f / l1;
    const int row0 = q0 + w * 16 + g;
    #pragma unroll
    for (int nt = 0; nt < 4; nt++) {
        int col = h * D_K + nt * 8 + 2 * tc;
        float f0 = ao[nt][0] * inv0, f1 = ao[nt][1] * inv0;
        float f2 = ao[nt][2] * inv1, f3 = ao[nt][3] * inv1;
        u32 lo01, lo23;
        u32 hi01 = pack_split(f0, f1, lo01);
        u32 hi23 = pack_split(f2, f3, lo23);
        size_t o0 = (size_t)(b * S_LEN + row0) * R_DIM + col;
        size_t o1 = (size_t)(b * S_LEN + row0 + 8) * R_DIM + col;
        *(u32*)&Oh[o0] = hi01;
        *(u32*)&Ol[o0] = lo01;
        *(u32*)&Oh[o1] = hi23;
        *(u32*)&Ol[o1] = lo23;
    }
}

// ---------------------------------------------------------------------------
extern "C" void kernel_launch(void* const* d_in, const int* in_sizes, int n_in,
                              void* d_out, int out_size)
{
    const float* x    = (const float*)d_in[0];
    const float* Wq   = (const float*)d_in[1];
    const float* bq   = (const float*)d_in[2];
    const float* Wk   = (const float*)d_in[3];
    const float* bk   = (const float*)d_in[4];
    const float* Wv   = (const float*)d_in[5];
    const float* bv   = (const float*)d_in[6];
    const float* Wo   = (const float*)d_in[7];
    const float* bo   = (const float*)d_in[8];
    const int*   mask = (const int*)d_in[9];
    float* out = (float*)d_out;

    float* f32base = nullptr;
    cudaGetSymbolAddress((void**)&f32base, g_f32);
    __nv_bfloat16* hib = nullptr;
    __nv_bfloat16* lob = nullptr;
    cudaGetSymbolAddress((void**)&hib, g_hi);
    cudaGetSymbolAddress((void**)&lob, g_lo);

    float* Qb = f32base;
    float* Kb = Qb + (size_t)M_ROWS * R_DIM;
    float* Vb = Kb + (size_t)M_ROWS * R_DIM;

    cudaFuncSetAttribute(qkv_hmma_kernel, cudaFuncAttributeMaxDynamicSharedMemorySize, SM_TOTAL);
    cudaFuncSetAttribute(outproj_hmma_kernel, cudaFuncAttributeMaxDynamicSharedMemorySize, SM_TOTAL);
    cudaFuncSetAttribute(attn_hmma_kernel, cudaFuncAttributeMaxDynamicSharedMemorySize, ATT_SMEM);

    // 1) fp32 -> bf16 hi/lo splits
    convert_split_kernel<<<2048, 256>>>(x,  hib + X_OFF,           lob + X_OFF,           (int)(8388608 / 4));
    convert_split_kernel<<<1024, 256>>>(Wq, hib + W_OFF,           lob + W_OFF,           (int)(WSZ / 4));
    convert_split_kernel<<<1024, 256>>>(Wk, hib + W_OFF + WSZ,     lob + W_OFF + WSZ,     (int)(WSZ / 4));
    convert_split_kernel<<<1024, 256>>>(Wv, hib + W_OFF + 2 * WSZ, lob + W_OFF + 2 * WSZ, (int)(WSZ / 4));
    convert_split_kernel<<<1024, 256>>>(Wo, hib + WO_OFF,          lob + WO_OFF,          (int)(WSZ / 4));

    // 2) QKV projections on HMMA (bf16 split, fp32 accumulate)
    dim3 g_qkv(R_DIM / BN, M_ROWS / BM, 3);
    qkv_hmma_kernel<<<g_qkv, 256, SM_TOTAL>>>(bq, bk, bv);

    // 3) flash attention on HMMA, emits bf16 hi/lo output
    dim3 g_attn(S_LEN / ATT_BQ, B_SZ * N_HEADS);
    attn_hmma_kernel<<<g_attn, 256, ATT_SMEM>>>(Qb, Kb, Vb, mask, hib + O_OFF, lob + O_OFF);

    // 4) output projection on HMMA
    dim3 g_out(D_MODEL / BN, M_ROWS / BM);
    outproj_hmma_kernel<<<g_out, 256, SM_TOTAL>>>(bo, out);
}

// round 8
// speedup vs baseline: 2.8598x; 1.0422x over previous
#include <cuda_runtime.h>
#include <cuda_bf16.h>
#include <cstdint>

#define D_MODEL 2048
#define R_DIM   512
#define N_HEADS 16
#define D_K     32
#define B_SZ    2
#define S_LEN   2048
#define M_ROWS  (B_SZ * S_LEN)   // 4096

typedef unsigned long long u64;
typedef uint32_t u32;

// ---------------------------------------------------------------------------
// bf16 hi/lo split storage:
//   x      : 4096*2048   @ 0
//   Wq/k/v : 3*512*2048  @ 8388608
//   Wo     : 2048*512    @ 11534336
//   O(attn): 4096*512    @ 12582912
//   Q/K/V  : 3*4096*512  @ 14680064   (Q pre-scaled by 1/sqrt(dk))
// ---------------------------------------------------------------------------
#define X_OFF   0ull
#define W_OFF   8388608ull
#define WSZ     1048576ull
#define WO_OFF  11534336ull
#define O_OFF   12582912ull
#define QKV_OFF 14680064ull
#define QKVSZ   2097152ull
#define SPLIT_TOTAL 20971520ull
__device__ __nv_bfloat16 g_hi[SPLIT_TOTAL];
__device__ __nv_bfloat16 g_lo[SPLIT_TOTAL];

// ---------------------------------------------------------------------------
// PTX helpers (base ISA only: mma.sync / ldmatrix / cp.async)
// ---------------------------------------------------------------------------
__device__ __forceinline__ u32 smem_u32(const void* p) {
    u32 a;
    asm("{ .reg .u64 t; cvta.to.shared.u64 t, %1; cvt.u32.u64 %0, t; }" : "=r"(a) : "l"(p));
    return a;
}
__device__ __forceinline__ void ldsm_x4(u32& r0, u32& r1, u32& r2, u32& r3, u32 addr) {
    asm volatile("ldmatrix.sync.aligned.m8n8.x4.shared.b16 {%0,%1,%2,%3}, [%4];"
                 : "=r"(r0), "=r"(r1), "=r"(r2), "=r"(r3) : "r"(addr));
}
__device__ __forceinline__ void ldsm_x4_t(u32& r0, u32& r1, u32& r2, u32& r3, u32 addr) {
    asm volatile("ldmatrix.sync.aligned.m8n8.x4.trans.shared.b16 {%0,%1,%2,%3}, [%4];"
                 : "=r"(r0), "=r"(r1), "=r"(r2), "=r"(r3) : "r"(addr));
}
__device__ __forceinline__ void mma_bf16(float* d, const u32* a, const u32* b) {
    asm volatile(
        "mma.sync.aligned.m16n8k16.row.col.f32.bf16.bf16.f32 "
        "{%0,%1,%2,%3}, {%4,%5,%6,%7}, {%8,%9}, {%0,%1,%2,%3};"
        : "+f"(d[0]), "+f"(d[1]), "+f"(d[2]), "+f"(d[3])
        : "r"(a[0]), "r"(a[1]), "r"(a[2]), "r"(a[3]), "r"(b[0]), "r"(b[1]));
}
__device__ __forceinline__ void cp16(u32 saddr, const void* g) {
    asm volatile("cp.async.cg.shared.global [%0], [%1], 16;" :: "r"(saddr), "l"(g) : "memory");
}
__device__ __forceinline__ void cp_commit() {
    asm volatile("cp.async.commit_group;" ::: "memory");
}
// pack two floats into bf16x2; residual pair returned in lo_out
__device__ __forceinline__ u32 pack_split(float x, float y, u32& lo_out) {
    __nv_bfloat162 h = __floats2bfloat162_rn(x, y);
    float hx = __bfloat162float(h.x), hy = __bfloat162float(h.y);
    __nv_bfloat162 l = __floats2bfloat162_rn(x - hx, y - hy);
    lo_out = *reinterpret_cast<u32*>(&l);
    return *reinterpret_cast<u32*>(&h);
}

// ---------------------------------------------------------------------------
// fp32 -> bf16 hi/lo split conversion
// ---------------------------------------------------------------------------
__global__ __launch_bounds__(256) void convert_split_kernel(
    const float* __restrict__ src, __nv_bfloat16* __restrict__ hi,
    __nv_bfloat16* __restrict__ lo, int n4)
{
    for (int i = blockIdx.x * blockDim.x + threadIdx.x; i < n4; i += gridDim.x * blockDim.x) {
        float4 v = ((const float4*)src)[i];
        __nv_bfloat16 h0 = __float2bfloat16(v.x);
        __nv_bfloat16 h1 = __float2bfloat16(v.y);
        __nv_bfloat16 h2 = __float2bfloat16(v.z);
        __nv_bfloat16 h3 = __float2bfloat16(v.w);
        __nv_bfloat16 l0 = __float2bfloat16(v.x - __bfloat162float(h0));
        __nv_bfloat16 l1 = __float2bfloat16(v.y - __bfloat162float(h1));
        __nv_bfloat16 l2 = __float2bfloat16(v.z - __bfloat162float(h2));
        __nv_bfloat16 l3 = __float2bfloat16(v.w - __bfloat162float(h3));
        __nv_bfloat162 ph0; ph0.x = h0; ph0.y = h1;
        __nv_bfloat162 ph1; ph1.x = h2; ph1.y = h3;
        __nv_bfloat162 pl0; pl0.x = l0; pl0.y = l1;
        __nv_bfloat162 pl1; pl1.x = l2; pl1.y = l3;
        ((__nv_bfloat162*)hi)[2 * i + 0] = ph0;
        ((__nv_bfloat162*)hi)[2 * i + 1] = ph1;
        ((__nv_bfloat162*)lo)[2 * i + 0] = pl0;
        ((__nv_bfloat162*)lo)[2 * i + 1] = pl1;
    }
}

// ---------------------------------------------------------------------------
// HMMA bf16-split GEMM. Mainloop unchanged (validated). Epilogue gains a
// split-write mode: outH/outL bf16 with scale (used by QKV), else fp32 C.
// ---------------------------------------------------------------------------
#define BM 128
#define BN 128
#define BK 64

#define TILE_B      (128 * 128)
#define STAGE_BYTES (4 * TILE_B)
#define SM_TOTAL    (2 * STAGE_BYTES)

__device__ __forceinline__ void gemm_hmma(
    const __nv_bfloat16* __restrict__ ah, const __nv_bfloat16* __restrict__ al,
    const __nv_bfloat16* __restrict__ bh, const __nv_bfloat16* __restrict__ bl,
    const float* __restrict__ bias, float* __restrict__ C,
    __nv_bfloat16* __restrict__ outH, __nv_bfloat16* __restrict__ outL, float oscale,
    int K, int ldc, int bm, int bn)
{
    extern __shared__ char smem[];
    const u32 sbase = smem_u32(smem);
    const int tid  = threadIdx.x;
    const int lane = tid & 31;
    const int wid  = tid >> 5;
    const int wm   = wid & 3;
    const int wn   = wid >> 2;

    float acc[2][8][4];
    #pragma unroll
    for (int mt = 0; mt < 2; mt++)
        #pragma unroll
        for (int nt = 0; nt < 8; nt++)
            #pragma unroll
            for (int r = 0; r < 4; r++) acc[mt][nt][r] = 0.f;

    auto load_stage = [&](int c, int stage) {
        const int k0 = c * BK;
        const u32 sb = sbase + stage * STAGE_BYTES;
        #pragma unroll
        for (int t = 0; t < 16; t++) {
            int i   = tid + t * 256;
            int arr = i >> 10;
            int ch  = i & 1023;
            int row = ch >> 3;
            int cc  = ch & 7;
            u32 soff = (u32)arr * TILE_B + (u32)row * 128 + (u32)((cc ^ (row & 7)) << 4);
            const __nv_bfloat16* g;
            if (arr == 0)      g = ah + (size_t)(bm + row) * K + k0 + cc * 8;
            else if (arr == 1) g = al + (size_t)(bm + row) * K + k0 + cc * 8;
            else if (arr == 2) g = bh + (size_t)(bn + row) * K + k0 + cc * 8;
            else               g = bl + (size_t)(bn + row) * K + k0 + cc * 8;
            cp16(sb + soff, g);
        }
        cp_commit();
    };

    auto compute_stage = [&](int stage) {
        const u32 sb = sbase + stage * STAGE_BYTES;
        #pragma unroll
        for (int ks = 0; ks < 4; ks++) {
            u32 a_h[2][4], a_l[2][4], b_h[8][2], b_l[8][2];
            #pragma unroll
            for (int mt = 0; mt < 2; mt++) {
                int row = wm * 32 + mt * 16 + (lane & 15);
                u32 koff = (u32)(((2 * ks + (lane >> 4)) ^ (row & 7)) << 4);
                u32 addr = sb + (u32)row * 128 + koff;
                ldsm_x4(a_h[mt][0], a_h[mt][1], a_h[mt][2], a_h[mt][3], addr);
                ldsm_x4(a_l[mt][0], a_l[mt][1], a_l[mt][2], a_l[mt][3], addr + TILE_B);
            }
            #pragma unroll
            for (int np = 0; np < 4; np++) {
                int row = wn * 64 + np * 16 + (lane & 15);
                u32 koff = (u32)(((2 * ks + (lane >> 4)) ^ (row & 7)) << 4);
                u32 addr = sb + 2u * TILE_B + (u32)row * 128 + koff;
                u32 r0, r1, r2, r3;
                ldsm_x4(r0, r1, r2, r3, addr);
                b_h[2 * np][0] = r0; b_h[2 * np][1] = r2;
                b_h[2 * np + 1][0] = r1; b_h[2 * np + 1][1] = r3;
                ldsm_x4(r0, r1, r2, r3, addr + TILE_B);
                b_l[2 * np][0] = r0; b_l[2 * np][1] = r2;
                b_l[2 * np + 1][0] = r1; b_l[2 * np + 1][1] = r3;
            }
            #pragma unroll
            for (int mt = 0; mt < 2; mt++)
                #pragma unroll
                for (int nt = 0; nt < 8; nt++) {
                    mma_bf16(acc[mt][nt], a_h[mt], b_h[nt]);
                    mma_bf16(acc[mt][nt], a_h[mt], b_l[nt]);
                    mma_bf16(acc[mt][nt], a_l[mt], b_h[nt]);
                }
        }
    };

    const int nch = K >> 6;
    load_stage(0, 0);
    for (int c = 0; c < nch; c++) {
        if (c + 1 < nch) {
            load_stage(c + 1, (c + 1) & 1);
            asm volatile("cp.async.wait_group 1;" ::: "memory");
        } else {
            asm volatile("cp.async.wait_group 0;" ::: "memory");
        }
        __syncthreads();
        compute_stage(c & 1);
        __syncthreads();
    }

    const int g  = lane >> 2;
    const int tc = lane & 3;
    if (outH) {
        #pragma unroll
        for (int mt = 0; mt < 2; mt++) {
            #pragma unroll
            for (int nt = 0; nt < 8; nt++) {
                int row = bm + wm * 32 + mt * 16 + g;
                int col = bn + wn * 64 + nt * 8 + 2 * tc;
                float b0 = bias[col], b1 = bias[col + 1];
                float f0 = (acc[mt][nt][0] + b0) * oscale;
                float f1 = (acc[mt][nt][1] + b1) * oscale;
                float f2 = (acc[mt][nt][2] + b0) * oscale;
                float f3 = (acc[mt][nt][3] + b1) * oscale;
                u32 lo01, lo23;
                u32 hi01 = pack_split(f0, f1, lo01);
                u32 hi23 = pack_split(f2, f3, lo23);
                size_t o0 = (size_t)row * ldc + col;
                size_t o1 = (size_t)(row + 8) * ldc + col;
                *(u32*)&outH[o0] = hi01; *(u32*)&outL[o0] = lo01;
                *(u32*)&outH[o1] = hi23; *(u32*)&outL[o1] = lo23;
            }
        }
    } else {
        #pragma unroll
        for (int mt = 0; mt < 2; mt++) {
            #pragma unroll
            for (int nt = 0; nt < 8; nt++) {
                int row = bm + wm * 32 + mt * 16 + g;
                int col = bn + wn * 64 + nt * 8 + 2 * tc;
                float b0 = bias[col], b1 = bias[col + 1];
                float2 v0; v0.x = acc[mt][nt][0] + b0; v0.y = acc[mt][nt][1] + b1;
                float2 v1; v1.x = acc[mt][nt][2] + b0; v1.y = acc[mt][nt][3] + b1;
                *(float2*)&C[(size_t)row * ldc + col]       = v0;
                *(float2*)&C[(size_t)(row + 8) * ldc + col] = v1;
            }
        }
    }
}

// QKV: writes bf16 hi/lo directly (Q pre-scaled by 1/sqrt(dk))
__global__ __launch_bounds__(256) void qkv_hmma_kernel(
    const float* __restrict__ bq, const float* __restrict__ bk, const float* __restrict__ bv)
{
    const int z = blockIdx.z;
    const float* bias = (z == 0) ? bq : (z == 1) ? bk : bv;
    const float scale = (z == 0) ? 0.17677669529663687f : 1.0f;
    gemm_hmma(g_hi + X_OFF, g_lo + X_OFF,
              g_hi + W_OFF + (size_t)z * WSZ, g_lo + W_OFF + (size_t)z * WSZ,
              bias, nullptr,
              g_hi + QKV_OFF + (size_t)z * QKVSZ, g_lo + QKV_OFF + (size_t)z * QKVSZ, scale,
              D_MODEL, R_DIM, blockIdx.y * BM, blockIdx.x * BN);
}

__global__ __launch_bounds__(256) void outproj_hmma_kernel(
    const float* __restrict__ bo, float* __restrict__ out)
{
    gemm_hmma(g_hi + O_OFF, g_lo + O_OFF,
              g_hi + WO_OFF, g_lo + WO_OFF,
              bo, out, nullptr, nullptr, 1.0f,
              R_DIM, D_MODEL, blockIdx.y * BM, blockIdx.x * BN);
}

// ---------------------------------------------------------------------------
// HMMA flash attention, bf16 hi/lo inputs via cp.async, 2-stage KV pipeline.
// CTA: 128 queries x one (b,h); 8 warps = 16 query rows each.
// ---------------------------------------------------------------------------
#define ATT_BQ  128
#define ATT_BKV 128
#define ROWB    80

#define AQ_H   0
#define AQ_L   10240
#define ASTG0  20480
#define ASTG   41472              // stage stride: 4*10240 + 512 mask
#define AS_KH  0
#define AS_KL  10240
#define AS_VH  20480
#define AS_VL  30720
#define AS_MSK 40960
#define ATT_SMEM (20480 + 2 * 41472)   // 103424

__global__ __launch_bounds__(256, 1) void attn_hmma_kernel(const int* __restrict__ mask)
{
    extern __shared__ char smem[];
    const u32 sb = smem_u32(smem);
    const int tid  = threadIdx.x;
    const int lane = tid & 31;
    const int w    = tid >> 5;
    const int bh   = blockIdx.y;
    const int b    = bh >> 4;
    const int h    = bh & 15;
    const int q0   = blockIdx.x * ATT_BQ;
    const int g    = lane >> 2;
    const int tc   = lane & 3;

    const __nv_bfloat16* Qh = g_hi + QKV_OFF;
    const __nv_bfloat16* Ql = g_lo + QKV_OFF;
    const __nv_bfloat16* Kh = g_hi + QKV_OFF + QKVSZ;
    const __nv_bfloat16* Kl = g_lo + QKV_OFF + QKVSZ;
    const __nv_bfloat16* Vh = g_hi + QKV_OFF + 2 * QKVSZ;
    const __nv_bfloat16* Vl = g_lo + QKV_OFF + 2 * QKVSZ;
    __nv_bfloat16* Oh = g_hi + O_OFF;
    __nv_bfloat16* Ol = g_lo + O_OFF;

    // ---- stage Q (1024 x 16B chunks across Qh/Ql) ----
    #pragma unroll
    for (int t = 0; t < 4; t++) {
        int c   = tid + t * 256;
        int arr = c >> 9;          // 0: hi, 1: lo
        int wch = c & 511;
        int row = wch >> 2;
        int prt = wch & 3;
        const __nv_bfloat16* src = (arr ? Ql : Qh)
            + (size_t)(b * S_LEN + q0 + row) * R_DIM + h * D_K + prt * 8;
        cp16(sb + (arr ? AQ_L : AQ_H) + row * ROWB + prt * 16, src);
    }
    cp_commit();

    // ---- KV stage loader (2048 x 16B KV chunks + 512B mask) ----
    auto load_kv = [&](int k0, int stage) {
        const u32 stg = sb + ASTG0 + stage * ASTG;
        #pragma unroll
        for (int t = 0; t < 8; t++) {
            int c   = tid + t * 256;
            int arr = c >> 9;      // 0:Kh 1:Kl 2:Vh 3:Vl
            int wch = c & 511;
            int row = wch >> 2;
            int prt = wch & 3;
            const __nv_bfloat16* src;
            if (arr == 0)      src = Kh;
            else if (arr == 1) src = Kl;
            else if (arr == 2) src = Vh;
            else               src = Vl;
            src += (size_t)(b * S_LEN + k0 + row) * R_DIM + h * D_K + prt * 8;
            cp16(stg + arr * 10240u + (u32)row * ROWB + (u32)prt * 16, src);
        }
        if (tid < 32)
            cp16(stg + AS_MSK + tid * 16, mask + b * S_LEN + k0 + tid * 4);
        cp_commit();
    };

    load_kv(0, 0);
    asm volatile("cp.async.wait_group 1;" ::: "memory");   // Q ready
    __syncthreads();

    // preload Q A-fragments
    u32 aqh[2][4], aql[2][4];
    #pragma unroll
    for (int kk = 0; kk < 2; kk++) {
        u32 addr = sb + AQ_H + (u32)(w * 16 + (lane & 15)) * ROWB + kk * 32 + (lane >> 4) * 16;
        ldsm_x4(aqh[kk][0], aqh[kk][1], aqh[kk][2], aqh[kk][3], addr);
        ldsm_x4(aql[kk][0], aql[kk][1], aql[kk][2], aql[kk][3], addr + (AQ_L - AQ_H));
    }

    float m0 = -1e30f, m1 = -1e30f, l0 = 0.f, l1 = 0.f;
    float ao[4][4];
    #pragma unroll
    for (int nt = 0; nt < 4; nt++)
        #pragma unroll
        for (int r = 0; r < 4; r++) ao[nt][r] = 0.f;

    const int nchunks = S_LEN / ATT_BKV;   // 16
    for (int c = 0; c < nchunks; c++) {
        if (c + 1 < nchunks) {
            load_kv((c + 1) * ATT_BKV, (c + 1) & 1);
            asm volatile("cp.async.wait_group 1;" ::: "memory");
        } else {
            asm volatile("cp.async.wait_group 0;" ::: "memory");
        }
        __syncthreads();
        const u32 stg = sb + ASTG0 + (c & 1) * ASTG;

        // ---- scores: 16(q) x 128(j), 3-pass split ----
        float sc[16][4];
        #pragma unroll
        for (int p8 = 0; p8 < 8; p8++) {
            #pragma unroll
            for (int r = 0; r < 4; r++) { sc[2 * p8][r] = 0.f; sc[2 * p8 + 1][r] = 0.f; }
            #pragma unroll
            for (int kk = 0; kk < 2; kk++) {
                u32 addr = stg + AS_KH + (u32)(p8 * 16 + (lane & 15)) * ROWB + kk * 32 + (lane >> 4) * 16;
                u32 rh0, rh1, rh2, rh3, rl0, rl1, rl2, rl3;
                ldsm_x4(rh0, rh1, rh2, rh3, addr);
                ldsm_x4(rl0, rl1, rl2, rl3, addr + (AS_KL - AS_KH));
                u32 beh[2] = {rh0, rh2}, boh[2] = {rh1, rh3};
                u32 bel[2] = {rl0, rl2}, bol[2] = {rl1, rl3};
                mma_bf16(sc[2 * p8], aqh[kk], beh);
                mma_bf16(sc[2 * p8], aqh[kk], bel);
                mma_bf16(sc[2 * p8], aql[kk], beh);
                mma_bf16(sc[2 * p8 + 1], aqh[kk], boh);
                mma_bf16(sc[2 * p8 + 1], aqh[kk], bol);
                mma_bf16(sc[2 * p8 + 1], aql[kk], boh);
            }
        }

        // ---- online softmax (rows g and g+8) ----
        float mt0 = m0, mt1 = m1;
        #pragma unroll
        for (int nt = 0; nt < 16; nt++) {
            int mi0 = *(const int*)(smem + (stg - sb) + AS_MSK + (nt * 8 + 2 * tc) * 4);
            int mi1 = *(const int*)(smem + (stg - sb) + AS_MSK + (nt * 8 + 2 * tc + 1) * 4);
            float md0 = mi0 ? 0.f : -1e30f;
            float md1 = mi1 ? 0.f : -1e30f;
            sc[nt][0] += md0; sc[nt][1] += md1;
            sc[nt][2] += md0; sc[nt][3] += md1;
            mt0 = fmaxf(mt0, fmaxf(sc[nt][0], sc[nt][1]));
            mt1 = fmaxf(mt1, fmaxf(sc[nt][2], sc[nt][3]));
        }
        mt0 = fmaxf(mt0, __shfl_xor_sync(0xFFFFFFFFu, mt0, 1));
        mt0 = fmaxf(mt0, __shfl_xor_sync(0xFFFFFFFFu, mt0, 2));
        mt1 = fmaxf(mt1, __shfl_xor_sync(0xFFFFFFFFu, mt1, 1));
        mt1 = fmaxf(mt1, __shfl_xor_sync(0xFFFFFFFFu, mt1, 2));
        float corr0 = __expf(m0 - mt0);
        float corr1 = __expf(m1 - mt1);
        m0 = mt0; m1 = mt1;
        float ls0 = 0.f, ls1 = 0.f;
        #pragma unroll
        for (int nt = 0; nt < 16; nt++) {
            sc[nt][0] = __expf(sc[nt][0] - m0);
            sc[nt][1] = __expf(sc[nt][1] - m0);
            sc[nt][2] = __expf(sc[nt][2] - m1);
            sc[nt][3] = __expf(sc[nt][3] - m1);
            ls0 += sc[nt][0] + sc[nt][1];
            ls1 += sc[nt][2] + sc[nt][3];
        }
        ls0 += __shfl_xor_sync(0xFFFFFFFFu, ls0, 1);
        ls0 += __shfl_xor_sync(0xFFFFFFFFu, ls0, 2);
        ls1 += __shfl_xor_sync(0xFFFFFFFFu, ls1, 1);
        ls1 += __shfl_xor_sync(0xFFFFFFFFu, ls1, 2);
        l0 = l0 * corr0 + ls0;
        l1 = l1 * corr1 + ls1;
        #pragma unroll
        for (int nt = 0; nt < 4; nt++) {
            ao[nt][0] *= corr0; ao[nt][1] *= corr0;
            ao[nt][2] *= corr1; ao[nt][3] *= corr1;
        }

        // ---- P @ V ----
        #pragma unroll
        for (int jc = 0; jc < 8; jc++) {
            u32 ah[4], al[4];
            ah[0] = pack_split(sc[2 * jc][0],     sc[2 * jc][1],     al[0]);
            ah[1] = pack_split(sc[2 * jc][2],     sc[2 * jc][3],     al[1]);
            ah[2] = pack_split(sc[2 * jc + 1][0], sc[2 * jc + 1][1], al[2]);
            ah[3] = pack_split(sc[2 * jc + 1][2], sc[2 * jc + 1][3], al[3]);
            #pragma unroll
            for (int np = 0; np < 2; np++) {
                u32 addr = stg + AS_VH
                         + (u32)(jc * 16 + ((lane >> 3) & 1) * 8 + (lane & 7)) * ROWB
                         + (u32)(np * 16 + (lane >> 4) * 8) * 2;
                u32 th0, th1, th2, th3, tl0, tl1, tl2, tl3;
                ldsm_x4_t(th0, th1, th2, th3, addr);
                ldsm_x4_t(tl0, tl1, tl2, tl3, addr + (AS_VL - AS_VH));
                u32 beh[2] = {th0, th1}, boh[2] = {th2, th3};
                u32 bel[2] = {tl0, tl1}, bol[2] = {tl2, tl3};
                mma_bf16(ao[2 * np], ah, beh);
                mma_bf16(ao[2 * np], ah, bel);
                mma_bf16(ao[2 * np], al, beh);
                mma_bf16(ao[2 * np + 1], ah, boh);
                mma_bf16(ao[2 * np + 1], ah, bol);
                mma_bf16(ao[2 * np + 1], al, boh);
            }
        }
        __syncthreads();
    }

    // ---- epilogue: O /= l, write bf16 hi/lo ----
    const float inv0 = 1.0f / l0;
    const float inv1 = 1.0f / l1;
    const int row0 = q0 + w * 16 + g;
    #pragma unroll
    for (int nt = 0; nt < 4; nt++) {
        int col = h * D_K + nt * 8 + 2 * tc;
        float f0 = ao[nt][0] * inv0, f1 = ao[nt][1] * inv0;
        float f2 = ao[nt][2] * inv1, f3 = ao[nt][3] * inv1;
        u32 lo01, lo23;
        u32 hi01 = pack_split(f0, f1, lo01);
        u32 hi23 = pack_split(f2, f3, lo23);
        size_t o0 = (size_t)(b * S_LEN + row0) * R_DIM + col;
        size_t o1 = (size_t)(b * S_LEN + row0 + 8) * R_DIM + col;
        *(u32*)&Oh[o0] = hi01;
        *(u32*)&Ol[o0] = lo01;
        *(u32*)&Oh[o1] = hi23;
        *(u32*)&Ol[o1] = lo23;
    }
}

// ---------------------------------------------------------------------------
extern "C" void kernel_launch(void* const* d_in, const int* in_sizes, int n_in,
                              void* d_out, int out_size)
{
    const float* x    = (const float*)d_in[0];
    const float* Wq   = (const float*)d_in[1];
    const float* bq   = (const float*)d_in[2];
    const float* Wk   = (const float*)d_in[3];
    const float* bk   = (const float*)d_in[4];
    const float* Wv   = (const float*)d_in[5];
    const float* bv   = (const float*)d_in[6];
    const float* Wo   = (const float*)d_in[7];
    const float* bo   = (const float*)d_in[8];
    const int*   mask = (const int*)d_in[9];
    float* out = (float*)d_out;

    __nv_bfloat16* hib = nullptr;
    __nv_bfloat16* lob = nullptr;
    cudaGetSymbolAddress((void**)&hib, g_hi);
    cudaGetSymbolAddress((void**)&lob, g_lo);

    cudaFuncSetAttribute(qkv_hmma_kernel, cudaFuncAttributeMaxDynamicSharedMemorySize, SM_TOTAL);
    cudaFuncSetAttribute(outproj_hmma_kernel, cudaFuncAttributeMaxDynamicSharedMemorySize, SM_TOTAL);
    cudaFuncSetAttribute(attn_hmma_kernel, cudaFuncAttributeMaxDynamicSharedMemorySize, ATT_SMEM);

    // 1) fp32 -> bf16 hi/lo splits (inputs + weights)
    convert_split_kernel<<<2048, 256>>>(x,  hib + X_OFF,           lob + X_OFF,           (int)(8388608 / 4));
    convert_split_kernel<<<1024, 256>>>(Wq, hib + W_OFF,           lob + W_OFF,           (int)(WSZ / 4));
    convert_split_kernel<<<1024, 256>>>(Wk, hib + W_OFF + WSZ,     lob + W_OFF + WSZ,     (int)(WSZ / 4));
    convert_split_kernel<<<1024, 256>>>(Wv, hib + W_OFF + 2 * WSZ, lob + W_OFF + 2 * WSZ, (int)(WSZ / 4));
    convert_split_kernel<<<1024, 256>>>(Wo, hib + WO_OFF,          lob + WO_OFF,          (int)(WSZ / 4));

    // 2) QKV projections (HMMA), writes bf16 hi/lo directly, Q pre-scaled
    dim3 g_qkv(R_DIM / BN, M_ROWS / BM, 3);
    qkv_hmma_kernel<<<g_qkv, 256, SM_TOTAL>>>(bq, bk, bv);

    // 3) flash attention (HMMA, cp.async double-buffered KV)
    dim3 g_attn(S_LEN / ATT_BQ, B_SZ * N_HEADS);
    attn_hmma_kernel<<<g_attn, 256, ATT_SMEM>>>(mask);

    // 4) output projection (HMMA)
    dim3 g_out(D_MODEL / BN, M_ROWS / BM);
    outproj_hmma_kernel<<<g_out, 256, SM_TOTAL>>>(bo, out);
}

// round 9
// speedup vs baseline: 2.9116x; 1.0181x over previous
#include <cuda_runtime.h>
#include <cuda_bf16.h>
#include <cstdint>

#define D_MODEL 2048
#define R_DIM   512
#define N_HEADS 16
#define D_K     32
#define B_SZ    2
#define S_LEN   2048
#define M_ROWS  (B_SZ * S_LEN)   // 4096

typedef unsigned long long u64;
typedef uint32_t u32;

// ---------------------------------------------------------------------------
// bf16 hi/lo split storage
// ---------------------------------------------------------------------------
#define X_OFF   0ull
#define W_OFF   8388608ull
#define WSZ     1048576ull
#define WO_OFF  11534336ull
#define O_OFF   12582912ull
#define QKV_OFF 14680064ull
#define QKVSZ   2097152ull
#define SPLIT_TOTAL 20971520ull
__device__ __nv_bfloat16 g_hi[SPLIT_TOTAL];
__device__ __nv_bfloat16 g_lo[SPLIT_TOTAL];

// ---------------------------------------------------------------------------
// PTX helpers (base ISA only: mma.sync / ldmatrix / cp.async)
// ---------------------------------------------------------------------------
__device__ __forceinline__ u32 smem_u32(const void* p) {
    u32 a;
    asm("{ .reg .u64 t; cvta.to.shared.u64 t, %1; cvt.u32.u64 %0, t; }" : "=r"(a) : "l"(p));
    return a;
}
__device__ __forceinline__ void ldsm_x4(u32& r0, u32& r1, u32& r2, u32& r3, u32 addr) {
    asm volatile("ldmatrix.sync.aligned.m8n8.x4.shared.b16 {%0,%1,%2,%3}, [%4];"
                 : "=r"(r0), "=r"(r1), "=r"(r2), "=r"(r3) : "r"(addr));
}
__device__ __forceinline__ void ldsm_x4_t(u32& r0, u32& r1, u32& r2, u32& r3, u32 addr) {
    asm volatile("ldmatrix.sync.aligned.m8n8.x4.trans.shared.b16 {%0,%1,%2,%3}, [%4];"
                 : "=r"(r0), "=r"(r1), "=r"(r2), "=r"(r3) : "r"(addr));
}
__device__ __forceinline__ void mma_bf16(float* d, const u32* a, const u32* b) {
    asm volatile(
        "mma.sync.aligned.m16n8k16.row.col.f32.bf16.bf16.f32 "
        "{%0,%1,%2,%3}, {%4,%5,%6,%7}, {%8,%9}, {%0,%1,%2,%3};"
        : "+f"(d[0]), "+f"(d[1]), "+f"(d[2]), "+f"(d[3])
        : "r"(a[0]), "r"(a[1]), "r"(a[2]), "r"(a[3]), "r"(b[0]), "r"(b[1]));
}
__device__ __forceinline__ void cp16(u32 saddr, const void* g) {
    asm volatile("cp.async.cg.shared.global [%0], [%1], 16;" :: "r"(saddr), "l"(g) : "memory");
}
__device__ __forceinline__ void cp_commit() {
    asm volatile("cp.async.commit_group;" ::: "memory");
}
__device__ __forceinline__ u32 pack_split(float x, float y, u32& lo_out) {
    __nv_bfloat162 h = __floats2bfloat162_rn(x, y);
    float hx = __bfloat162float(h.x), hy = __bfloat162float(h.y);
    __nv_bfloat162 l = __floats2bfloat162_rn(x - hx, y - hy);
    lo_out = *reinterpret_cast<u32*>(&l);
    return *reinterpret_cast<u32*>(&h);
}

// ---------------------------------------------------------------------------
// fp32 -> bf16 hi/lo split: single fused launch over x + 4 weight matrices
// segment float4 counts: x 2097152, each W 262144 (cumulative below)
// ---------------------------------------------------------------------------
__global__ __launch_bounds__(256) void convert_all_kernel(
    const float* __restrict__ x,  const float* __restrict__ Wq,
    const float* __restrict__ Wk, const float* __restrict__ Wv,
    const float* __restrict__ Wo)
{
    int i = blockIdx.x * blockDim.x + threadIdx.x;
    const float* src; size_t dst; int idx;
    if (i < 2097152)      { src = x;  dst = X_OFF;           idx = i; }
    else if (i < 2359296) { src = Wq; dst = W_OFF;           idx = i - 2097152; }
    else if (i < 2621440) { src = Wk; dst = W_OFF + WSZ;     idx = i - 2359296; }
    else if (i < 2883584) { src = Wv; dst = W_OFF + 2 * WSZ; idx = i - 2621440; }
    else                  { src = Wo; dst = WO_OFF;          idx = i - 2883584; }

    float4 v = ((const float4*)src)[idx];
    __nv_bfloat16 h0 = __float2bfloat16(v.x);
    __nv_bfloat16 h1 = __float2bfloat16(v.y);
    __nv_bfloat16 h2 = __float2bfloat16(v.z);
    __nv_bfloat16 h3 = __float2bfloat16(v.w);
    __nv_bfloat16 l0 = __float2bfloat16(v.x - __bfloat162float(h0));
    __nv_bfloat16 l1 = __float2bfloat16(v.y - __bfloat162float(h1));
    __nv_bfloat16 l2 = __float2bfloat16(v.z - __bfloat162float(h2));
    __nv_bfloat16 l3 = __float2bfloat16(v.w - __bfloat162float(h3));
    __nv_bfloat162 ph0; ph0.x = h0; ph0.y = h1;
    __nv_bfloat162 ph1; ph1.x = h2; ph1.y = h3;
    __nv_bfloat162 pl0; pl0.x = l0; pl0.y = l1;
    __nv_bfloat162 pl1; pl1.x = l2; pl1.y = l3;
    ((__nv_bfloat162*)(g_hi + dst))[2 * idx + 0] = ph0;
    ((__nv_bfloat162*)(g_hi + dst))[2 * idx + 1] = ph1;
    ((__nv_bfloat162*)(g_lo + dst))[2 * idx + 0] = pl0;
    ((__nv_bfloat162*)(g_lo + dst))[2 * idx + 1] = pl1;
}

// ---------------------------------------------------------------------------
// HMMA bf16-split GEMM: 3-stage cp.async pipeline, one sync per chunk.
// ---------------------------------------------------------------------------
#define BM 128
#define BN 128
#define BK 64

#define TILE_B      (128 * 128)
#define STAGE_BYTES (4 * TILE_B)          // 64 KB
#define SM_TOTAL    (3 * STAGE_BYTES)     // 192 KB

__device__ __forceinline__ void gemm_hmma(
    const __nv_bfloat16* __restrict__ ah, const __nv_bfloat16* __restrict__ al,
    const __nv_bfloat16* __restrict__ bh, const __nv_bfloat16* __restrict__ bl,
    const float* __restrict__ bias, float* __restrict__ C,
    __nv_bfloat16* __restrict__ outH, __nv_bfloat16* __restrict__ outL, float oscale,
    int K, int ldc, int bm, int bn)
{
    extern __shared__ char smem[];
    const u32 sbase = smem_u32(smem);
    const int tid  = threadIdx.x;
    const int lane = tid & 31;
    const int wid  = tid >> 5;
    const int wm   = wid & 3;
    const int wn   = wid >> 2;

    float acc[2][8][4];
    #pragma unroll
    for (int mt = 0; mt < 2; mt++)
        #pragma unroll
        for (int nt = 0; nt < 8; nt++)
            #pragma unroll
            for (int r = 0; r < 4; r++) acc[mt][nt][r] = 0.f;

    auto load_stage = [&](int c, int stage) {
        const int k0 = c * BK;
        const u32 sb = sbase + stage * STAGE_BYTES;
        #pragma unroll
        for (int t = 0; t < 16; t++) {
            int i   = tid + t * 256;
            int arr = i >> 10;
            int ch  = i & 1023;
            int row = ch >> 3;
            int cc  = ch & 7;
            u32 soff = (u32)arr * TILE_B + (u32)row * 128 + (u32)((cc ^ (row & 7)) << 4);
            const __nv_bfloat16* g;
            if (arr == 0)      g = ah + (size_t)(bm + row) * K + k0 + cc * 8;
            else if (arr == 1) g = al + (size_t)(bm + row) * K + k0 + cc * 8;
            else if (arr == 2) g = bh + (size_t)(bn + row) * K + k0 + cc * 8;
            else               g = bl + (size_t)(bn + row) * K + k0 + cc * 8;
            cp16(sb + soff, g);
        }
        cp_commit();
    };

    auto compute_stage = [&](int stage) {
        const u32 sb = sbase + stage * STAGE_BYTES;
        #pragma unroll
        for (int ks = 0; ks < 4; ks++) {
            u32 a_h[2][4], a_l[2][4], b_h[8][2], b_l[8][2];
            #pragma unroll
            for (int mt = 0; mt < 2; mt++) {
                int row = wm * 32 + mt * 16 + (lane & 15);
                u32 koff = (u32)(((2 * ks + (lane >> 4)) ^ (row & 7)) << 4);
                u32 addr = sb + (u32)row * 128 + koff;
                ldsm_x4(a_h[mt][0], a_h[mt][1], a_h[mt][2], a_h[mt][3], addr);
                ldsm_x4(a_l[mt][0], a_l[mt][1], a_l[mt][2], a_l[mt][3], addr + TILE_B);
            }
            #pragma unroll
            for (int np = 0; np < 4; np++) {
                int row = wn * 64 + np * 16 + (lane & 15);
                u32 koff = (u32)(((2 * ks + (lane >> 4)) ^ (row & 7)) << 4);
                u32 addr = sb + 2u * TILE_B + (u32)row * 128 + koff;
                u32 r0, r1, r2, r3;
                ldsm_x4(r0, r1, r2, r3, addr);
                b_h[2 * np][0] = r0; b_h[2 * np][1] = r2;
                b_h[2 * np + 1][0] = r1; b_h[2 * np + 1][1] = r3;
                ldsm_x4(r0, r1, r2, r3, addr + TILE_B);
                b_l[2 * np][0] = r0; b_l[2 * np][1] = r2;
                b_l[2 * np + 1][0] = r1; b_l[2 * np + 1][1] = r3;
            }
            #pragma unroll
            for (int mt = 0; mt < 2; mt++)
                #pragma unroll
                for (int nt = 0; nt < 8; nt++) {
                    mma_bf16(acc[mt][nt], a_h[mt], b_h[nt]);
                    mma_bf16(acc[mt][nt], a_h[mt], b_l[nt]);
                    mma_bf16(acc[mt][nt], a_l[mt], b_h[nt]);
                }
        }
    };

    const int nch = K >> 6;        // >= 8 always here
    load_stage(0, 0);
    load_stage(1, 1);
    int cur = 0;                   // stage of chunk c
    for (int c = 0; c < nch; c++) {
        if (c == nch - 1) {
            asm volatile("cp.async.wait_group 0;" ::: "memory");
        } else {
            asm volatile("cp.async.wait_group 1;" ::: "memory");
        }
        __syncthreads();
        if (c + 2 < nch) {
            int nxt2 = cur + 2; if (nxt2 >= 3) nxt2 -= 3;
            load_stage(c + 2, nxt2);
        }
        compute_stage(cur);
        if (++cur == 3) cur = 0;
    }

    const int g  = lane >> 2;
    const int tc = lane & 3;
    if (outH) {
        #pragma unroll
        for (int mt = 0; mt < 2; mt++) {
            #pragma unroll
            for (int nt = 0; nt < 8; nt++) {
                int row = bm + wm * 32 + mt * 16 + g;
                int col = bn + wn * 64 + nt * 8 + 2 * tc;
                float b0 = bias[col], b1 = bias[col + 1];
                float f0 = (acc[mt][nt][0] + b0) * oscale;
                float f1 = (acc[mt][nt][1] + b1) * oscale;
                float f2 = (acc[mt][nt][2] + b0) * oscale;
                float f3 = (acc[mt][nt][3] + b1) * oscale;
                u32 lo01, lo23;
                u32 hi01 = pack_split(f0, f1, lo01);
                u32 hi23 = pack_split(f2, f3, lo23);
                size_t o0 = (size_t)row * ldc + col;
                size_t o1 = (size_t)(row + 8) * ldc + col;
                *(u32*)&outH[o0] = hi01; *(u32*)&outL[o0] = lo01;
                *(u32*)&outH[o1] = hi23; *(u32*)&outL[o1] = lo23;
            }
        }
    } else {
        #pragma unroll
        for (int mt = 0; mt < 2; mt++) {
            #pragma unroll
            for (int nt = 0; nt < 8; nt++) {
                int row = bm + wm * 32 + mt * 16 + g;
                int col = bn + wn * 64 + nt * 8 + 2 * tc;
                float b0 = bias[col], b1 = bias[col + 1];
                float2 v0; v0.x = acc[mt][nt][0] + b0; v0.y = acc[mt][nt][1] + b1;
                float2 v1; v1.x = acc[mt][nt][2] + b0; v1.y = acc[mt][nt][3] + b1;
                *(float2*)&C[(size_t)row * ldc + col]       = v0;
                *(float2*)&C[(size_t)(row + 8) * ldc + col] = v1;
            }
        }
    }
}

__global__ __launch_bounds__(256) void qkv_hmma_kernel(
    const float* __restrict__ bq, const float* __restrict__ bk, const float* __restrict__ bv)
{
    const int z = blockIdx.z;
    const float* bias = (z == 0) ? bq : (z == 1) ? bk : bv;
    const float scale = (z == 0) ? 0.17677669529663687f : 1.0f;
    gemm_hmma(g_hi + X_OFF, g_lo + X_OFF,
              g_hi + W_OFF + (size_t)z * WSZ, g_lo + W_OFF + (size_t)z * WSZ,
              bias, nullptr,
              g_hi + QKV_OFF + (size_t)z * QKVSZ, g_lo + QKV_OFF + (size_t)z * QKVSZ, scale,
              D_MODEL, R_DIM, blockIdx.y * BM, blockIdx.x * BN);
}

__global__ __launch_bounds__(256) void outproj_hmma_kernel(
    const float* __restrict__ bo, float* __restrict__ out)
{
    gemm_hmma(g_hi + O_OFF, g_lo + O_OFF,
              g_hi + WO_OFF, g_lo + WO_OFF,
              bo, out, nullptr, nullptr, 1.0f,
              R_DIM, D_MODEL, blockIdx.y * BM, blockIdx.x * BN);
}

// ---------------------------------------------------------------------------
// HMMA flash attention: 3-stage cp.async KV pipeline, one sync per chunk.
// ---------------------------------------------------------------------------
#define ATT_BQ  128
#define ATT_BKV 128
#define ROWB    80

#define AQ_H   0
#define AQ_L   10240
#define ASTG0  20480
#define ASTG   41472              // stage: Kh,Kl,Vh,Vl (4*10240) + 512 mask
#define AS_KH  0
#define AS_KL  10240
#define AS_VH  20480
#define AS_VL  30720
#define AS_MSK 40960
#define ATT_SMEM (20480 + 3 * 41472)   // 144896

__global__ __launch_bounds__(256, 1) void attn_hmma_kernel(const int* __restrict__ mask)
{
    extern __shared__ char smem[];
    const u32 sb = smem_u32(smem);
    const int tid  = threadIdx.x;
    const int lane = tid & 31;
    const int w    = tid >> 5;
    const int bh   = blockIdx.y;
    const int b    = bh >> 4;
    const int h    = bh & 15;
    const int q0   = blockIdx.x * ATT_BQ;
    const int g    = lane >> 2;
    const int tc   = lane & 3;

    const __nv_bfloat16* Qh = g_hi + QKV_OFF;
    const __nv_bfloat16* Ql = g_lo + QKV_OFF;
    const __nv_bfloat16* Kh = g_hi + QKV_OFF + QKVSZ;
    const __nv_bfloat16* Kl = g_lo + QKV_OFF + QKVSZ;
    const __nv_bfloat16* Vh = g_hi + QKV_OFF + 2 * QKVSZ;
    const __nv_bfloat16* Vl = g_lo + QKV_OFF + 2 * QKVSZ;
    __nv_bfloat16* Oh = g_hi + O_OFF;
    __nv_bfloat16* Ol = g_lo + O_OFF;

    // ---- KV stage loader ----
    auto load_kv = [&](int k0, int stage) {
        const u32 stg = sb + ASTG0 + stage * ASTG;
        #pragma unroll
        for (int t = 0; t < 8; t++) {
            int c   = tid + t * 256;
            int arr = c >> 9;      // 0:Kh 1:Kl 2:Vh 3:Vl
            int wch = c & 511;
            int row = wch >> 2;
            int prt = wch & 3;
            const __nv_bfloat16* src;
            if (arr == 0)      src = Kh;
            else if (arr == 1) src = Kl;
            else if (arr == 2) src = Vh;
            else               src = Vl;
            src += (size_t)(b * S_LEN + k0 + row) * R_DIM + h * D_K + prt * 8;
            cp16(stg + arr * 10240u + (u32)row * ROWB + (u32)prt * 16, src);
        }
        if (tid < 32)
            cp16(stg + AS_MSK + tid * 16, mask + b * S_LEN + k0 + tid * 4);
        cp_commit();
    };

    // ---- prologue: Q stage, then KV stages 0 and 1 ----
    #pragma unroll
    for (int t = 0; t < 4; t++) {
        int c   = tid + t * 256;
        int arr = c >> 9;
        int wch = c & 511;
        int row = wch >> 2;
        int prt = wch & 3;
        const __nv_bfloat16* src = (arr ? Ql : Qh)
            + (size_t)(b * S_LEN + q0 + row) * R_DIM + h * D_K + prt * 8;
        cp16(sb + (arr ? AQ_L : AQ_H) + row * ROWB + prt * 16, src);
    }
    cp_commit();
    load_kv(0, 0);
    load_kv(ATT_BKV, 1);

    asm volatile("cp.async.wait_group 2;" ::: "memory");   // Q ready
    __syncthreads();

    u32 aqh[2][4], aql[2][4];
    #pragma unroll
    for (int kk = 0; kk < 2; kk++) {
        u32 addr = sb + AQ_H + (u32)(w * 16 + (lane & 15)) * ROWB + kk * 32 + (lane >> 4) * 16;
        ldsm_x4(aqh[kk][0], aqh[kk][1], aqh[kk][2], aqh[kk][3], addr);
        ldsm_x4(aql[kk][0], aql[kk][1], aql[kk][2], aql[kk][3], addr + (AQ_L - AQ_H));
    }

    float m0 = -1e30f, m1 = -1e30f, l0 = 0.f, l1 = 0.f;
    float ao[4][4];
    #pragma unroll
    for (int nt = 0; nt < 4; nt++)
        #pragma unroll
        for (int r = 0; r < 4; r++) ao[nt][r] = 0.f;

    const int nchunks = S_LEN / ATT_BKV;   // 16
    int cur = 0;
    for (int c = 0; c < nchunks; c++) {
        if (c == nchunks - 1) {
            asm volatile("cp.async.wait_group 0;" ::: "memory");
        } else {
            asm volatile("cp.async.wait_group 1;" ::: "memory");
        }
        __syncthreads();
        if (c + 2 < nchunks) {
            int nxt2 = cur + 2; if (nxt2 >= 3) nxt2 -= 3;
            load_kv((c + 2) * ATT_BKV, nxt2);
        }
        const u32 stg = sb + ASTG0 + cur * ASTG;
        const u32 stgoff = ASTG0 + cur * ASTG;

        // ---- scores ----
        float sc[16][4];
        #pragma unroll
        for (int p8 = 0; p8 < 8; p8++) {
            #pragma unroll
            for (int r = 0; r < 4; r++) { sc[2 * p8][r] = 0.f; sc[2 * p8 + 1][r] = 0.f; }
            #pragma unroll
            for (int kk = 0; kk < 2; kk++) {
                u32 addr = stg + AS_KH + (u32)(p8 * 16 + (lane & 15)) * ROWB + kk * 32 + (lane >> 4) * 16;
                u32 rh0, rh1, rh2, rh3, rl0, rl1, rl2, rl3;
                ldsm_x4(rh0, rh1, rh2, rh3, addr);
                ldsm_x4(rl0, rl1, rl2, rl3, addr + (AS_KL - AS_KH));
                u32 beh[2] = {rh0, rh2}, boh[2] = {rh1, rh3};
                u32 bel[2] = {rl0, rl2}, bol[2] = {rl1, rl3};
                mma_bf16(sc[2 * p8], aqh[kk], beh);
                mma_bf16(sc[2 * p8], aqh[kk], bel);
                mma_bf16(sc[2 * p8], aql[kk], beh);
                mma_bf16(sc[2 * p8 + 1], aqh[kk], boh);
                mma_bf16(sc[2 * p8 + 1], aqh[kk], bol);
                mma_bf16(sc[2 * p8 + 1], aql[kk], boh);
            }
        }

        // ---- online softmax ----
        float mt0 = m0, mt1 = m1;
        #pragma unroll
        for (int nt = 0; nt < 16; nt++) {
            int mi0 = *(const int*)(smem + stgoff + AS_MSK + (nt * 8 + 2 * tc) * 4);
            int mi1 = *(const int*)(smem + stgoff + AS_MSK + (nt * 8 + 2 * tc + 1) * 4);
            float md0 = mi0 ? 0.f : -1e30f;
            float md1 = mi1 ? 0.f : -1e30f;
            sc[nt][0] += md0; sc[nt][1] += md1;
            sc[nt][2] += md0; sc[nt][3] += md1;
            mt0 = fmaxf(mt0, fmaxf(sc[nt][0], sc[nt][1]));
            mt1 = fmaxf(mt1, fmaxf(sc[nt][2], sc[nt][3]));
        }
        mt0 = fmaxf(mt0, __shfl_xor_sync(0xFFFFFFFFu, mt0, 1));
        mt0 = fmaxf(mt0, __shfl_xor_sync(0xFFFFFFFFu, mt0, 2));
        mt1 = fmaxf(mt1, __shfl_xor_sync(0xFFFFFFFFu, mt1, 1));
        mt1 = fmaxf(mt1, __shfl_xor_sync(0xFFFFFFFFu, mt1, 2));
        float corr0 = __expf(m0 - mt0);
        float corr1 = __expf(m1 - mt1);
        m0 = mt0; m1 = mt1;
        float ls0 = 0.f, ls1 = 0.f;
        #pragma unroll
        for (int nt = 0; nt < 16; nt++) {
            sc[nt][0] = __expf(sc[nt][0] - m0);
            sc[nt][1] = __expf(sc[nt][1] - m0);
            sc[nt][2] = __expf(sc[nt][2] - m1);
            sc[nt][3] = __expf(sc[nt][3] - m1);
            ls0 += sc[nt][0] + sc[nt][1];
            ls1 += sc[nt][2] + sc[nt][3];
        }
        ls0 += __shfl_xor_sync(0xFFFFFFFFu, ls0, 1);
        ls0 += __shfl_xor_sync(0xFFFFFFFFu, ls0, 2);
        ls1 += __shfl_xor_sync(0xFFFFFFFFu, ls1, 1);
        ls1 += __shfl_xor_sync(0xFFFFFFFFu, ls1, 2);
        l0 = l0 * corr0 + ls0;
        l1 = l1 * corr1 + ls1;
        #pragma unroll
        for (int nt = 0; nt < 4; nt++) {
            ao[nt][0] *= corr0; ao[nt][1] *= corr0;
            ao[nt][2] *= corr1; ao[nt][3] *= corr1;
        }

        // ---- P @ V ----
        #pragma unroll
        for (int jc = 0; jc < 8; jc++) {
            u32 ah[4], al[4];
            ah[0] = pack_split(sc[2 * jc][0],     sc[2 * jc][1],     al[0]);
            ah[1] = pack_split(sc[2 * jc][2],     sc[2 * jc][3],     al[1]);
            ah[2] = pack_split(sc[2 * jc + 1][0], sc[2 * jc + 1][1], al[2]);
            ah[3] = pack_split(sc[2 * jc + 1][2], sc[2 * jc + 1][3], al[3]);
            #pragma unroll
            for (int np = 0; np < 2; np++) {
                u32 addr = stg + AS_VH
                         + (u32)(jc * 16 + ((lane >> 3) & 1) * 8 + (lane & 7)) * ROWB
                         + (u32)(np * 16 + (lane >> 4) * 8) * 2;
                u32 th0, th1, th2, th3, tl0, tl1, tl2, tl3;
                ldsm_x4_t(th0, th1, th2, th3, addr);
                ldsm_x4_t(tl0, tl1, tl2, tl3, addr + (AS_VL - AS_VH));
                u32 beh[2] = {th0, th1}, boh[2] = {th2, th3};
                u32 bel[2] = {tl0, tl1}, bol[2] = {tl2, tl3};
                mma_bf16(ao[2 * np], ah, beh);
                mma_bf16(ao[2 * np], ah, bel);
                mma_bf16(ao[2 * np], al, beh);
                mma_bf16(ao[2 * np + 1], ah, boh);
                mma_bf16(ao[2 * np + 1], ah, bol);
                mma_bf16(ao[2 * np + 1], al, boh);
            }
        }
        if (++cur == 3) cur = 0;
    }

    // ---- epilogue ----
    const float inv0 = 1.0f / l0;
    const float inv1 = 1.0f / l1;
    const int row0 = q0 + w * 16 + g;
    #pragma unroll
    for (int nt = 0; nt < 4; nt++) {
        int col = h * D_K + nt * 8 + 2 * tc;
        float f0 = ao[nt][0] * inv0, f1 = ao[nt][1] * inv0;
        float f2 = ao[nt][2] * inv1, f3 = ao[nt][3] * inv1;
        u32 lo01, lo23;
        u32 hi01 = pack_split(f0, f1, lo01);
        u32 hi23 = pack_split(f2, f3, lo23);
        size_t o0 = (size_t)(b * S_LEN + row0) * R_DIM + col;
        size_t o1 = (size_t)(b * S_LEN + row0 + 8) * R_DIM + col;
        *(u32*)&Oh[o0] = hi01;
        *(u32*)&Ol[o0] = lo01;
        *(u32*)&Oh[o1] = hi23;
        *(u32*)&Ol[o1] = lo23;
    }
}

// ---------------------------------------------------------------------------
extern "C" void kernel_launch(void* const* d_in, const int* in_sizes, int n_in,
                              void* d_out, int out_size)
{
    const float* x    = (const float*)d_in[0];
    const float* Wq   = (const float*)d_in[1];
    const float* bq   = (const float*)d_in[2];
    const float* Wk   = (const float*)d_in[3];
    const float* bk   = (const float*)d_in[4];
    const float* Wv   = (const float*)d_in[5];
    const float* bv   = (const float*)d_in[6];
    const float* Wo   = (const float*)d_in[7];
    const float* bo   = (const float*)d_in[8];
    const int*   mask = (const int*)d_in[9];
    float* out = (float*)d_out;

    cudaFuncSetAttribute(qkv_hmma_kernel, cudaFuncAttributeMaxDynamicSharedMemorySize, SM_TOTAL);
    cudaFuncSetAttribute(outproj_hmma_kernel, cudaFuncAttributeMaxDynamicSharedMemorySize, SM_TOTAL);
    cudaFuncSetAttribute(attn_hmma_kernel, cudaFuncAttributeMaxDynamicSharedMemorySize, ATT_SMEM);

    // 1) fp32 -> bf16 hi/lo splits, single fused launch (3145728 float4 total)
    convert_all_kernel<<<12288, 256>>>(x, Wq, Wk, Wv, Wo);

    // 2) QKV projections (HMMA), bf16 hi/lo output, Q pre-scaled
    dim3 g_qkv(R_DIM / BN, M_ROWS / BM, 3);
    qkv_hmma_kernel<<<g_qkv, 256, SM_TOTAL>>>(bq, bk, bv);

    // 3) flash attention (HMMA, 3-stage cp.async KV pipeline)
    dim3 g_attn(S_LEN / ATT_BQ, B_SZ * N_HEADS);
    attn_hmma_kernel<<<g_attn, 256, ATT_SMEM>>>(mask);

    // 4) output projection (HMMA)
    dim3 g_out(D_MODEL / BN, M_ROWS / BM);
    outproj_hmma_kernel<<<g_out, 256, SM_TOTAL>>>(bo, out);
}

// round 10
// speedup vs baseline: 2.9129x; 1.0005x over previous
#include <cuda_runtime.h>
#include <cuda_bf16.h>
#include <cstdint>

#define D_MODEL 2048
#define R_DIM   512
#define N_HEADS 16
#define D_K     32
#define B_SZ    2
#define S_LEN   2048
#define M_ROWS  (B_SZ * S_LEN)   // 4096

typedef unsigned long long u64;
typedef uint32_t u32;

// ---------------------------------------------------------------------------
// bf16 hi/lo split storage
// ---------------------------------------------------------------------------
#define X_OFF   0ull
#define W_OFF   8388608ull
#define WSZ     1048576ull
#define WO_OFF  11534336ull
#define O_OFF   12582912ull
#define QKV_OFF 14680064ull
#define QKVSZ   2097152ull
#define SPLIT_TOTAL 20971520ull
__device__ __nv_bfloat16 g_hi[SPLIT_TOTAL];
__device__ __nv_bfloat16 g_lo[SPLIT_TOTAL];

// ---------------------------------------------------------------------------
// PTX helpers (base ISA only: mma.sync / ldmatrix / cp.async)
// ---------------------------------------------------------------------------
__device__ __forceinline__ u32 smem_u32(const void* p) {
    u32 a;
    asm("{ .reg .u64 t; cvta.to.shared.u64 t, %1; cvt.u32.u64 %0, t; }" : "=r"(a) : "l"(p));
    return a;
}
__device__ __forceinline__ void ldsm_x4(u32& r0, u32& r1, u32& r2, u32& r3, u32 addr) {
    asm volatile("ldmatrix.sync.aligned.m8n8.x4.shared.b16 {%0,%1,%2,%3}, [%4];"
                 : "=r"(r0), "=r"(r1), "=r"(r2), "=r"(r3) : "r"(addr));
}
__device__ __forceinline__ void ldsm_x4_t(u32& r0, u32& r1, u32& r2, u32& r3, u32 addr) {
    asm volatile("ldmatrix.sync.aligned.m8n8.x4.trans.shared.b16 {%0,%1,%2,%3}, [%4];"
                 : "=r"(r0), "=r"(r1), "=r"(r2), "=r"(r3) : "r"(addr));
}
__device__ __forceinline__ void mma_bf16(float* d, const u32* a, const u32* b) {
    asm volatile(
        "mma.sync.aligned.m16n8k16.row.col.f32.bf16.bf16.f32 "
        "{%0,%1,%2,%3}, {%4,%5,%6,%7}, {%8,%9}, {%0,%1,%2,%3};"
        : "+f"(d[0]), "+f"(d[1]), "+f"(d[2]), "+f"(d[3])
        : "r"(a[0]), "r"(a[1]), "r"(a[2]), "r"(a[3]), "r"(b[0]), "r"(b[1]));
}
__device__ __forceinline__ void cp16(u32 saddr, const void* g) {
    asm volatile("cp.async.cg.shared.global [%0], [%1], 16;" :: "r"(saddr), "l"(g) : "memory");
}
__device__ __forceinline__ void cp_commit() {
    asm volatile("cp.async.commit_group;" ::: "memory");
}
__device__ __forceinline__ u32 pack_split(float x, float y, u32& lo_out) {
    __nv_bfloat162 h = __floats2bfloat162_rn(x, y);
    float hx = __bfloat162float(h.x), hy = __bfloat162float(h.y);
    __nv_bfloat162 l = __floats2bfloat162_rn(x - hx, y - hy);
    lo_out = *reinterpret_cast<u32*>(&l);
    return *reinterpret_cast<u32*>(&h);
}

// ---------------------------------------------------------------------------
// fp32 -> bf16 hi/lo split: single fused launch over x + 4 weight matrices
// segment float4 counts: x 2097152, each W 262144 (cumulative below)
// ---------------------------------------------------------------------------
__global__ __launch_bounds__(256) void convert_all_kernel(
    const float* __restrict__ x,  const float* __restrict__ Wq,
    const float* __restrict__ Wk, const float* __restrict__ Wv,
    const float* __restrict__ Wo)
{
    int i = blockIdx.x * blockDim.x + threadIdx.x;
    const float* src; size_t dst; int idx;
    if (i < 2097152)      { src = x;  dst = X_OFF;           idx = i; }
    else if (i < 2359296) { src = Wq; dst = W_OFF;           idx = i - 2097152; }
    else if (i < 2621440) { src = Wk; dst = W_OFF + WSZ;     idx = i - 2359296; }
    else if (i < 2883584) { src = Wv; dst = W_OFF + 2 * WSZ; idx = i - 2621440; }
    else                  { src = Wo; dst = WO_OFF;          idx = i - 2883584; }

    float4 v = ((const float4*)src)[idx];
    __nv_bfloat16 h0 = __float2bfloat16(v.x);
    __nv_bfloat16 h1 = __float2bfloat16(v.y);
    __nv_bfloat16 h2 = __float2bfloat16(v.z);
    __nv_bfloat16 h3 = __float2bfloat16(v.w);
    __nv_bfloat16 l0 = __float2bfloat16(v.x - __bfloat162float(h0));
    __nv_bfloat16 l1 = __float2bfloat16(v.y - __bfloat162float(h1));
    __nv_bfloat16 l2 = __float2bfloat16(v.z - __bfloat162float(h2));
    __nv_bfloat16 l3 = __float2bfloat16(v.w - __bfloat162float(h3));
    __nv_bfloat162 ph0; ph0.x = h0; ph0.y = h1;
    __nv_bfloat162 ph1; ph1.x = h2; ph1.y = h3;
    __nv_bfloat162 pl0; pl0.x = l0; pl0.y = l1;
    __nv_bfloat162 pl1; pl1.x = l2; pl1.y = l3;
    ((__nv_bfloat162*)(g_hi + dst))[2 * idx + 0] = ph0;
    ((__nv_bfloat162*)(g_hi + dst))[2 * idx + 1] = ph1;
    ((__nv_bfloat162*)(g_lo + dst))[2 * idx + 0] = pl0;
    ((__nv_bfloat162*)(g_lo + dst))[2 * idx + 1] = pl1;
}

// ---------------------------------------------------------------------------
// HMMA bf16-split GEMM: 3-stage cp.async pipeline, one sync per chunk.
// ---------------------------------------------------------------------------
#define BM 128
#define BN 128
#define BK 64

#define TILE_B      (128 * 128)
#define STAGE_BYTES (4 * TILE_B)          // 64 KB
#define SM_TOTAL    (3 * STAGE_BYTES)     // 192 KB

__device__ __forceinline__ void gemm_hmma(
    const __nv_bfloat16* __restrict__ ah, const __nv_bfloat16* __restrict__ al,
    const __nv_bfloat16* __restrict__ bh, const __nv_bfloat16* __restrict__ bl,
    const float* __restrict__ bias, float* __restrict__ C,
    __nv_bfloat16* __restrict__ outH, __nv_bfloat16* __restrict__ outL, float oscale,
    int K, int ldc, int bm, int bn)
{
    extern __shared__ char smem[];
    const u32 sbase = smem_u32(smem);
    const int tid  = threadIdx.x;
    const int lane = tid & 31;
    const int wid  = tid >> 5;
    const int wm   = wid & 3;
    const int wn   = wid >> 2;

    float acc[2][8][4];
    #pragma unroll
    for (int mt = 0; mt < 2; mt++)
        #pragma unroll
        for (int nt = 0; nt < 8; nt++)
            #pragma unroll
            for (int r = 0; r < 4; r++) acc[mt][nt][r] = 0.f;

    auto load_stage = [&](int c, int stage) {
        const int k0 = c * BK;
        const u32 sb = sbase + stage * STAGE_BYTES;
        #pragma unroll
        for (int t = 0; t < 16; t++) {
            int i   = tid + t * 256;
            int arr = i >> 10;
            int ch  = i & 1023;
            int row = ch >> 3;
            int cc  = ch & 7;
            u32 soff = (u32)arr * TILE_B + (u32)row * 128 + (u32)((cc ^ (row & 7)) << 4);
            const __nv_bfloat16* g;
            if (arr == 0)      g = ah + (size_t)(bm + row) * K + k0 + cc * 8;
            else if (arr == 1) g = al + (size_t)(bm + row) * K + k0 + cc * 8;
            else if (arr == 2) g = bh + (size_t)(bn + row) * K + k0 + cc * 8;
            else               g = bl + (size_t)(bn + row) * K + k0 + cc * 8;
            cp16(sb + soff, g);
        }
        cp_commit();
    };

    auto compute_stage = [&](int stage) {
        const u32 sb = sbase + stage * STAGE_BYTES;
        #pragma unroll
        for (int ks = 0; ks < 4; ks++) {
            u32 a_h[2][4], a_l[2][4], b_h[8][2], b_l[8][2];
            #pragma unroll
            for (int mt = 0; mt < 2; mt++) {
                int row = wm * 32 + mt * 16 + (lane & 15);
                u32 koff = (u32)(((2 * ks + (lane >> 4)) ^ (row & 7)) << 4);
                u32 addr = sb + (u32)row * 128 + koff;
                ldsm_x4(a_h[mt][0], a_h[mt][1], a_h[mt][2], a_h[mt][3], addr);
                ldsm_x4(a_l[mt][0], a_l[mt][1], a_l[mt][2], a_l[mt][3], addr + TILE_B);
            }
            #pragma unroll
            for (int np = 0; np < 4; np++) {
                int row = wn * 64 + np * 16 + (lane & 15);
                u32 koff = (u32)(((2 * ks + (lane >> 4)) ^ (row & 7)) << 4);
                u32 addr = sb + 2u * TILE_B + (u32)row * 128 + koff;
                u32 r0, r1, r2, r3;
                ldsm_x4(r0, r1, r2, r3, addr);
                b_h[2 * np][0] = r0; b_h[2 * np][1] = r2;
                b_h[2 * np + 1][0] = r1; b_h[2 * np + 1][1] = r3;
                ldsm_x4(r0, r1, r2, r3, addr + TILE_B);
                b_l[2 * np][0] = r0; b_l[2 * np][1] = r2;
                b_l[2 * np + 1][0] = r1; b_l[2 * np + 1][1] = r3;
            }
            #pragma unroll
            for (int mt = 0; mt < 2; mt++)
                #pragma unroll
                for (int nt = 0; nt < 8; nt++) {
                    mma_bf16(acc[mt][nt], a_h[mt], b_h[nt]);
                    mma_bf16(acc[mt][nt], a_h[mt], b_l[nt]);
                    mma_bf16(acc[mt][nt], a_l[mt], b_h[nt]);
                }
        }
    };

    const int nch = K >> 6;        // >= 8 always here
    load_stage(0, 0);
    load_stage(1, 1);
    int cur = 0;                   // stage of chunk c
    for (int c = 0; c < nch; c++) {
        if (c == nch - 1) {
            asm volatile("cp.async.wait_group 0;" ::: "memory");
        } else {
            asm volatile("cp.async.wait_group 1;" ::: "memory");
        }
        __syncthreads();
        if (c + 2 < nch) {
            int nxt2 = cur + 2; if (nxt2 >= 3) nxt2 -= 3;
            load_stage(c + 2, nxt2);
        }
        compute_stage(cur);
        if (++cur == 3) cur = 0;
    }

    const int g  = lane >> 2;
    const int tc = lane & 3;
    if (outH) {
        #pragma unroll
        for (int mt = 0; mt < 2; mt++) {
            #pragma unroll
            for (int nt = 0; nt < 8; nt++) {
                int row = bm + wm * 32 + mt * 16 + g;
                int col = bn + wn * 64 + nt * 8 + 2 * tc;
                float b0 = bias[col], b1 = bias[col + 1];
                float f0 = (acc[mt][nt][0] + b0) * oscale;
                float f1 = (acc[mt][nt][1] + b1) * oscale;
                float f2 = (acc[mt][nt][2] + b0) * oscale;
                float f3 = (acc[mt][nt][3] + b1) * oscale;
                u32 lo01, lo23;
                u32 hi01 = pack_split(f0, f1, lo01);
                u32 hi23 = pack_split(f2, f3, lo23);
                size_t o0 = (size_t)row * ldc + col;
                size_t o1 = (size_t)(row + 8) * ldc + col;
                *(u32*)&outH[o0] = hi01; *(u32*)&outL[o0] = lo01;
                *(u32*)&outH[o1] = hi23; *(u32*)&outL[o1] = lo23;
            }
        }
    } else {
        #pragma unroll
        for (int mt = 0; mt < 2; mt++) {
            #pragma unroll
            for (int nt = 0; nt < 8; nt++) {
                int row = bm + wm * 32 + mt * 16 + g;
                int col = bn + wn * 64 + nt * 8 + 2 * tc;
                float b0 = bias[col], b1 = bias[col + 1];
                float2 v0; v0.x = acc[mt][nt][0] + b0; v0.y = acc[mt][nt][1] + b1;
                float2 v1; v1.x = acc[mt][nt][2] + b0; v1.y = acc[mt][nt][3] + b1;
                *(float2*)&C[(size_t)row * ldc + col]       = v0;
                *(float2*)&C[(size_t)(row + 8) * ldc + col] = v1;
            }
        }
    }
}

__global__ __launch_bounds__(256) void qkv_hmma_kernel(
    const float* __restrict__ bq, const float* __restrict__ bk, const float* __restrict__ bv)
{
    const int z = blockIdx.z;
    const float* bias = (z == 0) ? bq : (z == 1) ? bk : bv;
    const float scale = (z == 0) ? 0.17677669529663687f : 1.0f;
    gemm_hmma(g_hi + X_OFF, g_lo + X_OFF,
              g_hi + W_OFF + (size_t)z * WSZ, g_lo + W_OFF + (size_t)z * WSZ,
              bias, nullptr,
              g_hi + QKV_OFF + (size_t)z * QKVSZ, g_lo + QKV_OFF + (size_t)z * QKVSZ, scale,
              D_MODEL, R_DIM, blockIdx.y * BM, blockIdx.x * BN);
}

__global__ __launch_bounds__(256) void outproj_hmma_kernel(
    const float* __restrict__ bo, float* __restrict__ out)
{
    gemm_hmma(g_hi + O_OFF, g_lo + O_OFF,
              g_hi + WO_OFF, g_lo + WO_OFF,
              bo, out, nullptr, nullptr, 1.0f,
              R_DIM, D_MODEL, blockIdx.y * BM, blockIdx.x * BN);
}

// ---------------------------------------------------------------------------
// HMMA flash attention: 3-stage cp.async KV pipeline, one sync per chunk.
// ---------------------------------------------------------------------------
#define ATT_BQ  128
#define ATT_BKV 128
#define ROWB    80

#define AQ_H   0
#define AQ_L   10240
#define ASTG0  20480
#define ASTG   41472              // stage: Kh,Kl,Vh,Vl (4*10240) + 512 mask
#define AS_KH  0
#define AS_KL  10240
#define AS_VH  20480
#define AS_VL  30720
#define AS_MSK 40960
#define ATT_SMEM (20480 + 3 * 41472)   // 144896

__global__ __launch_bounds__(256, 1) void attn_hmma_kernel(const int* __restrict__ mask)
{
    extern __shared__ char smem[];
    const u32 sb = smem_u32(smem);
    const int tid  = threadIdx.x;
    const int lane = tid & 31;
    const int w    = tid >> 5;
    const int bh   = blockIdx.y;
    const int b    = bh >> 4;
    const int h    = bh & 15;
    const int q0   = blockIdx.x * ATT_BQ;
    const int g    = lane >> 2;
    const int tc   = lane & 3;

    const __nv_bfloat16* Qh = g_hi + QKV_OFF;
    const __nv_bfloat16* Ql = g_lo + QKV_OFF;
    const __nv_bfloat16* Kh = g_hi + QKV_OFF + QKVSZ;
    const __nv_bfloat16* Kl = g_lo + QKV_OFF + QKVSZ;
    const __nv_bfloat16* Vh = g_hi + QKV_OFF + 2 * QKVSZ;
    const __nv_bfloat16* Vl = g_lo + QKV_OFF + 2 * QKVSZ;
    __nv_bfloat16* Oh = g_hi + O_OFF;
    __nv_bfloat16* Ol = g_lo + O_OFF;

    // ---- KV stage loader ----
    auto load_kv = [&](int k0, int stage) {
        const u32 stg = sb + ASTG0 + stage * ASTG;
        #pragma unroll
        for (int t = 0; t < 8; t++) {
            int c   = tid + t * 256;
            int arr = c >> 9;      // 0:Kh 1:Kl 2:Vh 3:Vl
            int wch = c & 511;
            int row = wch >> 2;
            int prt = wch & 3;
            const __nv_bfloat16* src;
            if (arr == 0)      src = Kh;
            else if (arr == 1) src = Kl;
            else if (arr == 2) src = Vh;
            else               src = Vl;
            src += (size_t)(b * S_LEN + k0 + row) * R_DIM + h * D_K + prt * 8;
            cp16(stg + arr * 10240u + (u32)row * ROWB + (u32)prt * 16, src);
        }
        if (tid < 32)
            cp16(stg + AS_MSK + tid * 16, mask + b * S_LEN + k0 + tid * 4);
        cp_commit();
    };

    // ---- prologue: Q stage, then KV stages 0 and 1 ----
    #pragma unroll
    for (int t = 0; t < 4; t++) {
        int c   = tid + t * 256;
        int arr = c >> 9;
        int wch = c & 511;
        int row = wch >> 2;
        int prt = wch & 3;
        const __nv_bfloat16* src = (arr ? Ql : Qh)
            + (size_t)(b * S_LEN + q0 + row) * R_DIM + h * D_K + prt * 8;
        cp16(sb + (arr ? AQ_L : AQ_H) + row * ROWB + prt * 16, src);
    }
    cp_commit();
    load_kv(0, 0);
    load_kv(ATT_BKV, 1);

    asm volatile("cp.async.wait_group 2;" ::: "memory");   // Q ready
    __syncthreads();

    u32 aqh[2][4], aql[2][4];
    #pragma unroll
    for (int kk = 0; kk < 2; kk++) {
        u32 addr = sb + AQ_H + (u32)(w * 16 + (lane & 15)) * ROWB + kk * 32 + (lane >> 4) * 16;
        ldsm_x4(aqh[kk][0], aqh[kk][1], aqh[kk][2], aqh[kk][3], addr);
        ldsm_x4(aql[kk][0], aql[kk][1], aql[kk][2], aql[kk][3], addr + (AQ_L - AQ_H));
    }

    float m0 = -1e30f, m1 = -1e30f, l0 = 0.f, l1 = 0.f;
    float ao[4][4];
    #pragma unroll
    for (int nt = 0; nt < 4; nt++)
        #pragma unroll
        for (int r = 0; r < 4; r++) ao[nt][r] = 0.f;

    const int nchunks = S_LEN / ATT_BKV;   // 16
    int cur = 0;
    for (int c = 0; c < nchunks; c++) {
        if (c == nchunks - 1) {
            asm volatile("cp.async.wait_group 0;" ::: "memory");
        } else {
            asm volatile("cp.async.wait_group 1;" ::: "memory");
        }
        __syncthreads();
        if (c + 2 < nchunks) {
            int nxt2 = cur + 2; if (nxt2 >= 3) nxt2 -= 3;
            load_kv((c + 2) * ATT_BKV, nxt2);
        }
        const u32 stg = sb + ASTG0 + cur * ASTG;
        const u32 stgoff = ASTG0 + cur * ASTG;

        // ---- scores ----
        float sc[16][4];
        #pragma unroll
        for (int p8 = 0; p8 < 8; p8++) {
            #pragma unroll
            for (int r = 0; r < 4; r++) { sc[2 * p8][r] = 0.f; sc[2 * p8 + 1][r] = 0.f; }
            #pragma unroll
            for (int kk = 0; kk < 2; kk++) {
                u32 addr = stg + AS_KH + (u32)(p8 * 16 + (lane & 15)) * ROWB + kk * 32 + (lane >> 4) * 16;
                u32 rh0, rh1, rh2, rh3, rl0, rl1, rl2, rl3;
                ldsm_x4(rh0, rh1, rh2, rh3, addr);
                ldsm_x4(rl0, rl1, rl2, rl3, addr + (AS_KL - AS_KH));
                u32 beh[2] = {rh0, rh2}, boh[2] = {rh1, rh3};
                u32 bel[2] = {rl0, rl2}, bol[2] = {rl1, rl3};
                mma_bf16(sc[2 * p8], aqh[kk], beh);
                mma_bf16(sc[2 * p8], aqh[kk], bel);
                mma_bf16(sc[2 * p8], aql[kk], beh);
                mma_bf16(sc[2 * p8 + 1], aqh[kk], boh);
                mma_bf16(sc[2 * p8 + 1], aqh[kk], bol);
                mma_bf16(sc[2 * p8 + 1], aql[kk], boh);
            }
        }

        // ---- online softmax ----
        float mt0 = m0, mt1 = m1;
        #pragma unroll
        for (int nt = 0; nt < 16; nt++) {
            int mi0 = *(const int*)(smem + stgoff + AS_MSK + (nt * 8 + 2 * tc) * 4);
            int mi1 = *(const int*)(smem + stgoff + AS_MSK + (nt * 8 + 2 * tc + 1) * 4);
            float md0 = mi0 ? 0.f : -1e30f;
            float md1 = mi1 ? 0.f : -1e30f;
            sc[nt][0] += md0; sc[nt][1] += md1;
            sc[nt][2] += md0; sc[nt][3] += md1;
            mt0 = fmaxf(mt0, fmaxf(sc[nt][0], sc[nt][1]));
            mt1 = fmaxf(mt1, fmaxf(sc[nt][2], sc[nt][3]));
        }
        mt0 = fmaxf(mt0, __shfl_xor_sync(0xFFFFFFFFu, mt0, 1));
        mt0 = fmaxf(mt0, __shfl_xor_sync(0xFFFFFFFFu, mt0, 2));
        mt1 = fmaxf(mt1, __shfl_xor_sync(0xFFFFFFFFu, mt1, 1));
        mt1 = fmaxf(mt1, __shfl_xor_sync(0xFFFFFFFFu, mt1, 2));
        float corr0 = __expf(m0 - mt0);
        float corr1 = __expf(m1 - mt1);
        m0 = mt0; m1 = mt1;
        float ls0 = 0.f, ls1 = 0.f;
        #pragma unroll
        for (int nt = 0; nt < 16; nt++) {
            sc[nt][0] = __expf(sc[nt][0] - m0);
            sc[nt][1] = __expf(sc[nt][1] - m0);
            sc[nt][2] = __expf(sc[nt][2] - m1);
            sc[nt][3] = __expf(sc[nt][3] - m1);
            ls0 += sc[nt][0] + sc[nt][1];
            ls1 += sc[nt][2] + sc[nt][3];
        }
        ls0 += __shfl_xor_sync(0xFFFFFFFFu, ls0, 1);
        ls0 += __shfl_xor_sync(0xFFFFFFFFu, ls0, 2);
        ls1 += __shfl_xor_sync(0xFFFFFFFFu, ls1, 1);
        ls1 += __shfl_xor_sync(0xFFFFFFFFu, ls1, 2);
        l0 = l0 * corr0 + ls0;
        l1 = l1 * corr1 + ls1;
        #pragma unroll
        for (int nt = 0; nt < 4; nt++) {
            ao[nt][0] *= corr0; ao[nt][1] *= corr0;
            ao[nt][2] *= corr1; ao[nt][3] *= corr1;
        }

        // ---- P @ V ----
        #pragma unroll
        for (int jc = 0; jc < 8; jc++) {
            u32 ah[4], al[4];
            ah[0] = pack_split(sc[2 * jc][0],     sc[2 * jc][1],     al[0]);
            ah[1] = pack_split(sc[2 * jc][2],     sc[2 * jc][3],     al[1]);
            ah[2] = pack_split(sc[2 * jc + 1][0], sc[2 * jc + 1][1], al[2]);
            ah[3] = pack_split(sc[2 * jc + 1][2], sc[2 * jc + 1][3], al[3]);
            #pragma unroll
            for (int np = 0; np < 2; np++) {
                u32 addr = stg + AS_VH
                         + (u32)(jc * 16 + ((lane >> 3) & 1) * 8 + (lane & 7)) * ROWB
                         + (u32)(np * 16 + (lane >> 4) * 8) * 2;
                u32 th0, th1, th2, th3, tl0, tl1, tl2, tl3;
                ldsm_x4_t(th0, th1, th2, th3, addr);
                ldsm_x4_t(tl0, tl1, tl2, tl3, addr + (AS_VL - AS_VH));
                u32 beh[2] = {th0, th1}, boh[2] = {th2, th3};
                u32 bel[2] = {tl0, tl1}, bol[2] = {tl2, tl3};
                mma_bf16(ao[2 * np], ah, beh);
                mma_bf16(ao[2 * np], ah, bel);
                mma_bf16(ao[2 * np], al, beh);
                mma_bf16(ao[2 * np + 1], ah, boh);
                mma_bf16(ao[2 * np + 1], ah, bol);
                mma_bf16(ao[2 * np + 1], al, boh);
            }
        }
        if (++cur == 3) cur = 0;
    }

    // ---- epilogue ----
    const float inv0 = 1.0f / l0;
    const float inv1 = 1.0f / l1;
    const int row0 = q0 + w * 16 + g;
    #pragma unroll
    for (int nt = 0; nt < 4; nt++) {
        int col = h * D_K + nt * 8 + 2 * tc;
        float f0 = ao[nt][0] * inv0, f1 = ao[nt][1] * inv0;
        float f2 = ao[nt][2] * inv1, f3 = ao[nt][3] * inv1;
        u32 lo01, lo23;
        u32 hi01 = pack_split(f0, f1, lo01);
        u32 hi23 = pack_split(f2, f3, lo23);
        size_t o0 = (size_t)(b * S_LEN + row0) * R_DIM + col;
        size_t o1 = (size_t)(b * S_LEN + row0 + 8) * R_DIM + col;
        *(u32*)&Oh[o0] = hi01;
        *(u32*)&Ol[o0] = lo01;
        *(u32*)&Oh[o1] = hi23;
        *(u32*)&Ol[o1] = lo23;
    }
}

// ---------------------------------------------------------------------------
extern "C" void kernel_launch(void* const* d_in, const int* in_sizes, int n_in,
                              void* d_out, int out_size)
{
    const float* x    = (const float*)d_in[0];
    const float* Wq   = (const float*)d_in[1];
    const float* bq   = (const float*)d_in[2];
    const float* Wk   = (const float*)d_in[3];
    const float* bk   = (const float*)d_in[4];
    const float* Wv   = (const float*)d_in[5];
    const float* bv   = (const float*)d_in[6];
    const float* Wo   = (const float*)d_in[7];
    const float* bo   = (const float*)d_in[8];
    const int*   mask = (const int*)d_in[9];
    float* out = (float*)d_out;

    cudaFuncSetAttribute(qkv_hmma_kernel, cudaFuncAttributeMaxDynamicSharedMemorySize, SM_TOTAL);
    cudaFuncSetAttribute(outproj_hmma_kernel, cudaFuncAttributeMaxDynamicSharedMemorySize, SM_TOTAL);
    cudaFuncSetAttribute(attn_hmma_kernel, cudaFuncAttributeMaxDynamicSharedMemorySize, ATT_SMEM);

    // 1) fp32 -> bf16 hi/lo splits, single fused launch (3145728 float4 total)
    convert_all_kernel<<<12288, 256>>>(x, Wq, Wk, Wv, Wo);

    // 2) QKV projections (HMMA), bf16 hi/lo output, Q pre-scaled
    dim3 g_qkv(R_DIM / BN, M_ROWS / BM, 3);
    qkv_hmma_kernel<<<g_qkv, 256, SM_TOTAL>>>(bq, bk, bv);

    // 3) flash attention (HMMA, 3-stage cp.async KV pipeline)
    dim3 g_attn(S_LEN / ATT_BQ, B_SZ * N_HEADS);
    attn_hmma_kernel<<<g_attn, 256, ATT_SMEM>>>(mask);

    // 4) output projection (HMMA)
    dim3 g_out(D_MODEL / BN, M_ROWS / BM);
    outproj_hmma_kernel<<<g_out, 256, SM_TOTAL>>>(bo, out);
}